// round 6
// baseline (speedup 1.0000x reference)
#include <cuda_runtime.h>
#include <math.h>

#define NN    100000
#define NNP   100096          // padded to multiple of 128
#define NE    1600000
#define INF   128
#define HID   64
#define OUTF  40
#define GRD   8
#define NFT   1024            // features: f = i*16 + branch*8 + k
#define KT    64              // f per tile
#define KTI   (NFT/KT)        // 16 tiles

typedef unsigned long long ull;

// Scratch (no cudaMalloc allowed)
__device__ float g_bufA[(size_t)NNP * HID];
__device__ float g_bufB[(size_t)NNP * HID];
__device__ float g_Bt[2][NFT * HID];   // transposed coeffs: Bt[f*64 + j]
__device__ int   g_colstart[NN + 1];
__device__ int   g_cnt[NN];
__device__ int   g_cur[NN];
__device__ ull   g_edges[NE];          // packed (w<<32 | row), CSC-ordered by col

// ---------------- f32x2 helpers ----------------
__device__ __forceinline__ ull pk2(float s) {
    ull d; unsigned u = __float_as_uint(s);
    asm("mov.b64 %0, {%1,%1};" : "=l"(d) : "r"(u));
    return d;
}
__device__ __forceinline__ void fma2(ull& d, ull a, ull b) {
    asm("fma.rn.f32x2 %0, %1, %2, %0;" : "+l"(d) : "l"(a), "l"(b));
}
__device__ __forceinline__ float2 up2(ull v) {
    unsigned lo, hi;
    asm("mov.b64 {%0,%1}, %2;" : "=r"(lo), "=r"(hi) : "l"(v));
    return make_float2(__uint_as_float(lo), __uint_as_float(hi));
}

// ---------------------------------------------------------------------------
// CSC build: zero counts -> histogram(col) -> scan -> scatter (row,w by col)
// ---------------------------------------------------------------------------
__global__ __launch_bounds__(256) void zero_cnt_kernel()
{
    int i = blockIdx.x * 256 + threadIdx.x;
    if (i < NN) g_cnt[i] = 0;
}

__global__ __launch_bounds__(256) void hist_kernel(const int* __restrict__ ecol)
{
    int e = blockIdx.x * 256 + threadIdx.x;
    atomicAdd(&g_cnt[ecol[e]], 1);
}

__global__ __launch_bounds__(1024) void scan_kernel()
{
    __shared__ int sh[1024];
    const int tid = threadIdx.x;
    const int CH  = (NN + 1023) / 1024;        // 98
    int lo = min(tid * CH, NN);
    int hi = min(lo + CH, NN);

    int s = 0;
    for (int i = lo; i < hi; i++) s += g_cnt[i];
    sh[tid] = s;
    __syncthreads();
    for (int off = 1; off < 1024; off <<= 1) {
        int v = (tid >= off) ? sh[tid - off] : 0;
        __syncthreads();
        if (tid >= off) sh[tid] += v;
        __syncthreads();
    }
    int run = sh[tid] - s;                     // exclusive prefix
    for (int i = lo; i < hi; i++) {
        g_colstart[i] = run;
        g_cur[i]      = run;
        run += g_cnt[i];
    }
    if (tid == 1023) g_colstart[NN] = run;     // == NE
}

__global__ __launch_bounds__(256) void scatter_kernel(
    const int* __restrict__ erow, const int* __restrict__ ecol,
    const float* __restrict__ ew)
{
    int e = blockIdx.x * 256 + threadIdx.x;
    int c = ecol[e];
    unsigned r = (unsigned)erow[e];
    unsigned w = __float_as_uint(ew[e]);
    int pos = atomicAdd(&g_cur[c], 1);
    g_edges[pos] = ((ull)w << 32) | (ull)r;
}

// ---------------------------------------------------------------------------
// CSC spmm: for each source node c, v = in[c] loaded ONCE; for each out-edge
// (r,w): out[r] += w*v via red.v4. Warp per source node; half-warp per edge.
// Gather traffic: 25.6 MB/pass (was 410 MB).
// ---------------------------------------------------------------------------
__global__ __launch_bounds__(256) void spmm_csc_kernel(
    const float* __restrict__ xin, float* __restrict__ xout)
{
    const int c    = blockIdx.x * 8 + (threadIdx.x >> 5);
    const int lane = threadIdx.x & 31;
    const int half = lane >> 4;           // 0 or 1
    const int l16  = lane & 15;

    if (c >= NN) return;
    int s = g_colstart[c];
    int e = g_colstart[c + 1];

    // load source row once: lanes 0-15 cover 64 floats; lanes 16-31 duplicate
    float4 v = __ldg(reinterpret_cast<const float4*>(xin + (size_t)c * HID) + l16);

    // two edges in flight per warp iteration (one per half-warp)
    for (int i = s + half; i < e; i += 2) {
        ull p = __ldg(g_edges + i);
        int   r  = (int)(unsigned)p;
        float wv = __uint_as_float((unsigned)(p >> 32));
        float* dst = xout + (size_t)r * HID + l16 * 4;
        asm volatile("red.global.add.v4.f32 [%0], {%1,%2,%3,%4};"
                     :: "l"(dst), "f"(v.x * wv), "f"(v.y * wv),
                        "f"(v.z * wv), "f"(v.w * wv) : "memory");
    }
}

// ---------------------------------------------------------------------------
__global__ __launch_bounds__(256) void zeroB_kernel()
{
    size_t t = (size_t)blockIdx.x * 256 + threadIdx.x;   // float4 index
    reinterpret_cast<float4*>(g_bufB)[t] = make_float4(0.f, 0.f, 0.f, 0.f);
}

// ---------------------------------------------------------------------------
// Transpose coeff [2][64][64][8] -> Bt[1024][64], f = i*16 + b*8 + k
// ---------------------------------------------------------------------------
__global__ __launch_bounds__(256) void transpose_coeff(
    const float* __restrict__ c, float* __restrict__ Bt)
{
    int idx = blockIdx.x * 256 + threadIdx.x;   // over 1024*64
    int j = idx & 63;
    int f = idx >> 6;
    int i = f >> 4, b = (f >> 3) & 1, k = f & 7;
    Bt[idx] = c[(((size_t)b * HID + j) * HID + i) * GRD + k];
}

// ---------------------------------------------------------------------------
// h = x @ W_in + b_in   -> bufA.  W staged in SMEM, f32x2 math.
// ---------------------------------------------------------------------------
__global__ __launch_bounds__(256) void lin_in_kernel(
    const float* __restrict__ x, const float* __restrict__ W,
    const float* __restrict__ b)
{
    __shared__ float xs[16][INF];
    __shared__ float ws[INF * HID];       // 32 KB
    const int n0  = blockIdx.x * 16;
    const int tid = threadIdx.x;

    for (int idx = tid; idx < INF * HID / 4; idx += 256)
        reinterpret_cast<float4*>(ws)[idx] =
            reinterpret_cast<const float4*>(W)[idx];
    for (int idx = tid; idx < 16 * INF; idx += 256) {
        int n = idx >> 7, c = idx & 127;
        xs[n][c] = x[(size_t)(n0 + n) * INF + c];
    }
    __syncthreads();

    const int j4 = (tid & 15) * 4;
    const int ny = tid >> 4;
    const int n  = n0 + ny;

    ull a01 = 0ULL, a23 = 0ULL;
#pragma unroll 8
    for (int i = 0; i < INF; i++) {
        ull xv = pk2(xs[ny][i]);
        const ull* w2 = reinterpret_cast<const ull*>(ws + i * HID + j4);
        fma2(a01, xv, w2[0]);
        fma2(a23, xv, w2[1]);
    }
    float2 v01 = up2(a01), v23 = up2(a23);
    *reinterpret_cast<float4*>(g_bufA + (size_t)n * HID + j4) =
        make_float4(v01.x + b[j4], v01.y + b[j4 + 1],
                    v23.x + b[j4 + 2], v23.y + b[j4 + 3]);
}

// ---------------------------------------------------------------------------
// Fourier KAN as SMEM-tiled GEMM with f32x2 packed math. (R2 version)
// CTA: 128 nodes x 64 j. 128 threads, thread tile = 8 nodes (4 pairs) x 8 j.
// ---------------------------------------------------------------------------
__global__ __launch_bounds__(128) void kan_kernel(
    const float* __restrict__ xin, const float* __restrict__ Bt,
    float* __restrict__ xout)
{
    extern __shared__ float sm[];
    float* sx = sm;                       // 64*129
    float* ft = sx + HID * 129;           // 64*128
    float* ct = ft + KT * 128;            // 64*64

    const int tid = threadIdx.x;
    const int n0  = blockIdx.x * 128;
    const int ng  = tid & 15;             // node-pair group
    const int jg  = tid >> 4;             // j group (0..7)

#pragma unroll
    for (int r = 0; r < 64; r++) {
        int idx = r * 128 + tid;
        int i = idx & 63;
        int n = idx >> 6;
        sx[i * 129 + n] = xin[(size_t)(n0 + n) * HID + i];
    }
    __syncthreads();

    ull acc[8][4];
#pragma unroll
    for (int jj = 0; jj < 8; jj++)
#pragma unroll
        for (int p = 0; p < 4; p++) acc[jj][p] = 0ULL;

    for (int kt = 0; kt < KTI; kt++) {
#pragma unroll
        for (int r = 0; r < 4; r++) {
            int idx = tid + 128 * r;
            int n  = idx & 127;
            int ii = idx >> 7;
            float xv = sx[(kt * 4 + ii) * 129 + n];
            float s1, c1;
            sincosf(xv, &s1, &c1);
            float* fcp = ft + (ii * 16) * 128 + n;
            float* fsp = fcp + 8 * 128;
            float twoc = 2.f * c1;
            float cp = 1.f, spv = 0.f, ck = c1, sk = s1;
            fcp[0] = c1; fsp[0] = s1;
#pragma unroll
            for (int k = 1; k < 8; k++) {
                float cn = twoc * ck - cp;
                float sn = twoc * sk - spv;
                cp = ck; spv = sk; ck = cn; sk = sn;
                fcp[k * 128] = ck; fsp[k * 128] = sk;
            }
        }
        {
            const float4* src = reinterpret_cast<const float4*>(Bt + kt * (KT * HID));
            float4* dst = reinterpret_cast<float4*>(ct);
#pragma unroll
            for (int r = 0; r < 8; r++) dst[tid + 128 * r] = src[tid + 128 * r];
        }
        __syncthreads();

#pragma unroll 4
        for (int f = 0; f < KT; f++) {
            const float* ftf = ft + f * 128;
            ull x0 = *reinterpret_cast<const ull*>(ftf + (ng     ) * 2);
            ull x1 = *reinterpret_cast<const ull*>(ftf + (ng + 16) * 2);
            ull x2 = *reinterpret_cast<const ull*>(ftf + (ng + 32) * 2);
            ull x3 = *reinterpret_cast<const ull*>(ftf + (ng + 48) * 2);
            const float* ctf = ct + f * HID + jg * 8;
            float4 cA = *reinterpret_cast<const float4*>(ctf);
            float4 cB = *reinterpret_cast<const float4*>(ctf + 4);
            ull c0 = pk2(cA.x), c1 = pk2(cA.y), c2 = pk2(cA.z), c3 = pk2(cA.w);
            ull c4 = pk2(cB.x), c5 = pk2(cB.y), c6 = pk2(cB.z), c7 = pk2(cB.w);
            fma2(acc[0][0], c0, x0); fma2(acc[0][1], c0, x1); fma2(acc[0][2], c0, x2); fma2(acc[0][3], c0, x3);
            fma2(acc[1][0], c1, x0); fma2(acc[1][1], c1, x1); fma2(acc[1][2], c1, x2); fma2(acc[1][3], c1, x3);
            fma2(acc[2][0], c2, x0); fma2(acc[2][1], c2, x1); fma2(acc[2][2], c2, x2); fma2(acc[2][3], c2, x3);
            fma2(acc[3][0], c3, x0); fma2(acc[3][1], c3, x1); fma2(acc[3][2], c3, x2); fma2(acc[3][3], c3, x3);
            fma2(acc[4][0], c4, x0); fma2(acc[4][1], c4, x1); fma2(acc[4][2], c4, x2); fma2(acc[4][3], c4, x3);
            fma2(acc[5][0], c5, x0); fma2(acc[5][1], c5, x1); fma2(acc[5][2], c5, x2); fma2(acc[5][3], c5, x3);
            fma2(acc[6][0], c6, x0); fma2(acc[6][1], c6, x1); fma2(acc[6][2], c6, x2); fma2(acc[6][3], c6, x3);
            fma2(acc[7][0], c7, x0); fma2(acc[7][1], c7, x1); fma2(acc[7][2], c7, x2); fma2(acc[7][3], c7, x3);
        }
        __syncthreads();
    }

#pragma unroll
    for (int p = 0; p < 4; p++) {
        int node = n0 + (ng + p * 16) * 2;
        float r0[8], r1[8];
#pragma unroll
        for (int jj = 0; jj < 8; jj++) {
            float2 v = up2(acc[jj][p]);
            r0[jj] = v.x; r1[jj] = v.y;
        }
        float4* d0 = reinterpret_cast<float4*>(xout + (size_t)node * HID + jg * 8);
        d0[0] = make_float4(r0[0], r0[1], r0[2], r0[3]);
        d0[1] = make_float4(r0[4], r0[5], r0[6], r0[7]);
        float4* d1 = reinterpret_cast<float4*>(xout + (size_t)(node + 1) * HID + jg * 8);
        d1[0] = make_float4(r1[0], r1[1], r1[2], r1[3]);
        d1[1] = make_float4(r1[4], r1[5], r1[6], r1[7]);
    }
}

// ---------------------------------------------------------------------------
// out = log_softmax(h @ W_out). Warp per node, 8 nodes/CTA, all-SMEM inner loop.
// ---------------------------------------------------------------------------
__global__ __launch_bounds__(256) void out_kernel(
    const float* __restrict__ Wout, float* __restrict__ out)
{
    __shared__ float wsh[HID * OUTF];     // 10 KB
    __shared__ float hsh[8][HID];
    const int tid  = threadIdx.x;
    const int nloc = tid >> 5;
    const int n    = blockIdx.x * 8 + nloc;
    const int lane = tid & 31;

    for (int idx = tid; idx < HID * OUTF; idx += 256) wsh[idx] = Wout[idx];
    for (int idx = tid; idx < 8 * HID; idx += 256) {
        int nl = idx >> 6, i = idx & 63;
        hsh[nl][i] = g_bufA[(size_t)(blockIdx.x * 8 + nl) * HID + i];
    }
    __syncthreads();

    float o0 = 0.f, o1 = 0.f;
#pragma unroll 8
    for (int i = 0; i < HID; i++) {
        float hv = hsh[nloc][i];
        o0 += hv * wsh[i * OUTF + lane];
        if (lane < 8) o1 += hv * wsh[i * OUTF + 32 + lane];
    }

    float m = (lane < 8) ? fmaxf(o0, o1) : o0;
#pragma unroll
    for (int off = 16; off; off >>= 1)
        m = fmaxf(m, __shfl_xor_sync(0xFFFFFFFFu, m, off));

    float e = expf(o0 - m) + ((lane < 8) ? expf(o1 - m) : 0.f);
#pragma unroll
    for (int off = 16; off; off >>= 1)
        e += __shfl_xor_sync(0xFFFFFFFFu, e, off);

    float ls = m + logf(e);
    out[(size_t)n * OUTF + lane] = o0 - ls;
    if (lane < 8) out[(size_t)n * OUTF + 32 + lane] = o1 - ls;
}

// ---------------------------------------------------------------------------
extern "C" void kernel_launch(void* const* d_in, const int* in_sizes, int n_in,
                              void* d_out, int out_size)
{
    const float* x     = (const float*)d_in[0];
    const int*   erow  = (const int*)  d_in[1];
    const int*   ecol  = (const int*)  d_in[2];
    const float* ew    = (const float*)d_in[3];
    const float* W_in  = (const float*)d_in[4];
    const float* b_in  = (const float*)d_in[5];
    const float* c1    = (const float*)d_in[6];
    const float* c2    = (const float*)d_in[7];
    const float* W_out = (const float*)d_in[8];
    float* out = (float*)d_out;

    float *bufA = nullptr, *bufB = nullptr, *Bt = nullptr;
    cudaGetSymbolAddress((void**)&bufA, g_bufA);
    cudaGetSymbolAddress((void**)&bufB, g_bufB);
    cudaGetSymbolAddress((void**)&Bt,   g_Bt);

    const int KAN_SMEM = (HID * 129 + KT * 128 + KT * HID) * (int)sizeof(float);
    cudaFuncSetAttribute(kan_kernel,
                         cudaFuncAttributeMaxDynamicSharedMemorySize, KAN_SMEM);

    const int zeroBlocks = (NNP * HID / 4) / 256;
    const int kanBlocks  = NNP / 128;
    const int cscBlocks  = (NN + 7) / 8;

    // CSC build (keyed on col; deterministic structure, allocation-free)
    zero_cnt_kernel<<<(NN + 255) / 256, 256>>>();
    hist_kernel<<<NE / 256, 256>>>(ecol);
    scan_kernel<<<1, 1024>>>();
    scatter_kernel<<<NE / 256, 256>>>(erow, ecol, ew);

    // coeff transpose + lin_in
    transpose_coeff<<<256, 256>>>(c1, Bt);
    transpose_coeff<<<256, 256>>>(c2, Bt + NFT * HID);
    lin_in_kernel<<<NN / 16, 256>>>(x, W_in, b_in);

    // pipeline
    zeroB_kernel<<<zeroBlocks, 256>>>();
    spmm_csc_kernel<<<cscBlocks, 256>>>(bufA, bufB);
    kan_kernel<<<kanBlocks, 128, KAN_SMEM>>>(bufB, Bt, bufA);
    zeroB_kernel<<<zeroBlocks, 256>>>();
    spmm_csc_kernel<<<cscBlocks, 256>>>(bufA, bufB);
    kan_kernel<<<kanBlocks, 128, KAN_SMEM>>>(bufB, Bt + NFT * HID, bufA);
    out_kernel<<<NN / 8, 256>>>(W_out, out);
}

// round 7
// speedup vs baseline: 1.2161x; 1.2161x over previous
#include <cuda_runtime.h>
#include <math.h>

#define NN    100000
#define NNP   100096          // padded to multiple of 128
#define NE    1600000
#define INF   128
#define HID   64
#define OUTF  40
#define GRD   8
#define NFT   1024            // features: f = i*16 + branch*8 + k
#define KT    64              // f per tile
#define KTI   (NFT/KT)        // 16 tiles
#define NB    391             // ceil(NN/256)

typedef unsigned long long ull;

// Scratch (no cudaMalloc; __device__ globals are zero-initialized)
__device__ float g_bufA[(size_t)NNP * HID];
__device__ float g_bufB[(size_t)NNP * HID];
__device__ float g_Bt[2][NFT * HID];   // transposed coeffs: Bt[f*64 + j]
__device__ int   g_rowstart[NN + 1];
__device__ int   g_cnt[NN];            // must be 0 at start of every launch
__device__ int   g_cur[NN];
__device__ int   g_locpre[NN];
__device__ int   g_bsum[NB];
__device__ ull   g_edges[NE];          // packed (w<<32 | col), CSR-ordered by row

// ---------------- f32x2 helpers ----------------
__device__ __forceinline__ ull pk2(float s) {
    ull d; unsigned u = __float_as_uint(s);
    asm("mov.b64 %0, {%1,%1};" : "=l"(d) : "r"(u));
    return d;
}
__device__ __forceinline__ void fma2(ull& d, ull a, ull b) {
    asm("fma.rn.f32x2 %0, %1, %2, %0;" : "+l"(d) : "l"(a), "l"(b));
}
__device__ __forceinline__ float2 up2(ull v) {
    unsigned lo, hi;
    asm("mov.b64 {%0,%1}, %2;" : "=r"(lo), "=r"(hi) : "l"(v));
    return make_float2(__uint_as_float(lo), __uint_as_float(hi));
}

// ---------------------------------------------------------------------------
// CSR build
// ---------------------------------------------------------------------------
__global__ __launch_bounds__(256) void hist_kernel(const int* __restrict__ erow)
{
    int e = blockIdx.x * 256 + threadIdx.x;
    atomicAdd(&g_cnt[erow[e]], 1);
}

// block-local exclusive scan of cnt; per-block totals to g_bsum
__global__ __launch_bounds__(256) void scanA_kernel()
{
    __shared__ int sh[256];
    const int b = blockIdx.x, tid = threadIdx.x;
    const int i = b * 256 + tid;
    int v = (i < NN) ? g_cnt[i] : 0;
    sh[tid] = v;
    __syncthreads();
    for (int off = 1; off < 256; off <<= 1) {
        int t = (tid >= off) ? sh[tid - off] : 0;
        __syncthreads();
        if (tid >= off) sh[tid] += t;
        __syncthreads();
    }
    if (i < NN) g_locpre[i] = sh[tid] - v;     // exclusive local prefix
    if (tid == 255) g_bsum[b] = sh[255];
}

// add block offsets; init rowstart + cur
__global__ __launch_bounds__(256) void scanB_kernel()
{
    __shared__ int bs[NB];
    __shared__ int off;
    const int b = blockIdx.x, tid = threadIdx.x;
    for (int j = tid; j < NB; j += 256) bs[j] = g_bsum[j];
    __syncthreads();
    if (tid == 0) {
        int s = 0;
        for (int j = 0; j < b; j++) s += bs[j];
        off = s;
    }
    __syncthreads();
    int i = b * 256 + tid;
    if (i < NN) {
        int rs = off + g_locpre[i];
        g_rowstart[i] = rs;
        g_cur[i]      = rs;
        if (i == NN - 1) g_rowstart[NN] = rs + g_cnt[i];
    }
}

__global__ __launch_bounds__(256) void scatter_kernel(
    const int* __restrict__ erow, const int* __restrict__ ecol,
    const float* __restrict__ ew)
{
    int e = blockIdx.x * 256 + threadIdx.x;
    int r = erow[e];
    unsigned c = (unsigned)ecol[e];
    unsigned w = __float_as_uint(ew[e]);
    int pos = atomicAdd(&g_cur[r], 1);
    g_edges[pos] = ((ull)w << 32) | (ull)c;
}

// re-arm counters for the next replay (runs LAST; first call uses static zeros)
__global__ __launch_bounds__(256) void zero_cnt_kernel()
{
    int i = blockIdx.x * 256 + threadIdx.x;
    if (i < NN) g_cnt[i] = 0;
}

// ---------------------------------------------------------------------------
// CSR spmm v2: warp per destination row, lane = 2 features, unroll-8 gather.
// No atomics, one coalesced store. Rows >= NN never written (stay zero).
// ---------------------------------------------------------------------------
__global__ __launch_bounds__(256) void spmm_csr_kernel(
    const float* __restrict__ xin, float* __restrict__ xout)
{
    const int node = blockIdx.x * 8 + (threadIdx.x >> 5);
    const int lane = threadIdx.x & 31;
    if (node >= NN) return;

    const int s = g_rowstart[node];
    const int e = g_rowstart[node + 1];
    const ull* __restrict__ xin2 = reinterpret_cast<const ull*>(xin);

    ull acc = 0ULL;
    int i = s;
    for (; i + 8 <= e; i += 8) {
        ull p0 = __ldg(g_edges + i + 0), p1 = __ldg(g_edges + i + 1);
        ull p2 = __ldg(g_edges + i + 2), p3 = __ldg(g_edges + i + 3);
        ull p4 = __ldg(g_edges + i + 4), p5 = __ldg(g_edges + i + 5);
        ull p6 = __ldg(g_edges + i + 6), p7 = __ldg(g_edges + i + 7);
        ull v0 = __ldg(xin2 + (size_t)(unsigned)p0 * 32 + lane);
        ull v1 = __ldg(xin2 + (size_t)(unsigned)p1 * 32 + lane);
        ull v2 = __ldg(xin2 + (size_t)(unsigned)p2 * 32 + lane);
        ull v3 = __ldg(xin2 + (size_t)(unsigned)p3 * 32 + lane);
        ull v4 = __ldg(xin2 + (size_t)(unsigned)p4 * 32 + lane);
        ull v5 = __ldg(xin2 + (size_t)(unsigned)p5 * 32 + lane);
        ull v6 = __ldg(xin2 + (size_t)(unsigned)p6 * 32 + lane);
        ull v7 = __ldg(xin2 + (size_t)(unsigned)p7 * 32 + lane);
        fma2(acc, pk2(__uint_as_float((unsigned)(p0 >> 32))), v0);
        fma2(acc, pk2(__uint_as_float((unsigned)(p1 >> 32))), v1);
        fma2(acc, pk2(__uint_as_float((unsigned)(p2 >> 32))), v2);
        fma2(acc, pk2(__uint_as_float((unsigned)(p3 >> 32))), v3);
        fma2(acc, pk2(__uint_as_float((unsigned)(p4 >> 32))), v4);
        fma2(acc, pk2(__uint_as_float((unsigned)(p5 >> 32))), v5);
        fma2(acc, pk2(__uint_as_float((unsigned)(p6 >> 32))), v6);
        fma2(acc, pk2(__uint_as_float((unsigned)(p7 >> 32))), v7);
    }
    for (; i + 2 <= e; i += 2) {
        ull p0 = __ldg(g_edges + i + 0), p1 = __ldg(g_edges + i + 1);
        ull v0 = __ldg(xin2 + (size_t)(unsigned)p0 * 32 + lane);
        ull v1 = __ldg(xin2 + (size_t)(unsigned)p1 * 32 + lane);
        fma2(acc, pk2(__uint_as_float((unsigned)(p0 >> 32))), v0);
        fma2(acc, pk2(__uint_as_float((unsigned)(p1 >> 32))), v1);
    }
    if (i < e) {
        ull p = __ldg(g_edges + i);
        ull v = __ldg(xin2 + (size_t)(unsigned)p * 32 + lane);
        fma2(acc, pk2(__uint_as_float((unsigned)(p >> 32))), v);
    }
    reinterpret_cast<ull*>(xout)[(size_t)node * 32 + lane] = acc;
}

// ---------------------------------------------------------------------------
// Transpose coeff [2][64][64][8] -> Bt[1024][64], f = i*16 + b*8 + k
// ---------------------------------------------------------------------------
__global__ __launch_bounds__(256) void transpose_coeff(
    const float* __restrict__ c, float* __restrict__ Bt)
{
    int idx = blockIdx.x * 256 + threadIdx.x;
    int j = idx & 63;
    int f = idx >> 6;
    int i = f >> 4, b = (f >> 3) & 1, k = f & 7;
    Bt[idx] = c[(((size_t)b * HID + j) * HID + i) * GRD + k];
}

// ---------------------------------------------------------------------------
// h = x @ W_in + b_in -> bufA
// ---------------------------------------------------------------------------
__global__ __launch_bounds__(256) void lin_in_kernel(
    const float* __restrict__ x, const float* __restrict__ W,
    const float* __restrict__ b)
{
    __shared__ float xs[16][INF];
    __shared__ float ws[INF * HID];
    const int n0  = blockIdx.x * 16;
    const int tid = threadIdx.x;

    for (int idx = tid; idx < INF * HID / 4; idx += 256)
        reinterpret_cast<float4*>(ws)[idx] =
            reinterpret_cast<const float4*>(W)[idx];
    for (int idx = tid; idx < 16 * INF; idx += 256) {
        int n = idx >> 7, c = idx & 127;
        xs[n][c] = x[(size_t)(n0 + n) * INF + c];
    }
    __syncthreads();

    const int j4 = (tid & 15) * 4;
    const int ny = tid >> 4;
    const int n  = n0 + ny;

    ull a01 = 0ULL, a23 = 0ULL;
#pragma unroll 8
    for (int i = 0; i < INF; i++) {
        ull xv = pk2(xs[ny][i]);
        const ull* w2 = reinterpret_cast<const ull*>(ws + i * HID + j4);
        fma2(a01, xv, w2[0]);
        fma2(a23, xv, w2[1]);
    }
    float2 v01 = up2(a01), v23 = up2(a23);
    *reinterpret_cast<float4*>(g_bufA + (size_t)n * HID + j4) =
        make_float4(v01.x + b[j4], v01.y + b[j4 + 1],
                    v23.x + b[j4 + 2], v23.y + b[j4 + 3]);
}

// ---------------------------------------------------------------------------
// Fourier KAN as SMEM-tiled GEMM with f32x2 packed math. (R2 version)
// ---------------------------------------------------------------------------
__global__ __launch_bounds__(128) void kan_kernel(
    const float* __restrict__ xin, const float* __restrict__ Bt,
    float* __restrict__ xout)
{
    extern __shared__ float sm[];
    float* sx = sm;                       // 64*129
    float* ft = sx + HID * 129;           // 64*128
    float* ct = ft + KT * 128;            // 64*64

    const int tid = threadIdx.x;
    const int n0  = blockIdx.x * 128;
    const int ng  = tid & 15;
    const int jg  = tid >> 4;

#pragma unroll
    for (int r = 0; r < 64; r++) {
        int idx = r * 128 + tid;
        int i = idx & 63;
        int n = idx >> 6;
        sx[i * 129 + n] = xin[(size_t)(n0 + n) * HID + i];
    }
    __syncthreads();

    ull acc[8][4];
#pragma unroll
    for (int jj = 0; jj < 8; jj++)
#pragma unroll
        for (int p = 0; p < 4; p++) acc[jj][p] = 0ULL;

    for (int kt = 0; kt < KTI; kt++) {
#pragma unroll
        for (int r = 0; r < 4; r++) {
            int idx = tid + 128 * r;
            int n  = idx & 127;
            int ii = idx >> 7;
            float xv = sx[(kt * 4 + ii) * 129 + n];
            float s1, c1;
            sincosf(xv, &s1, &c1);
            float* fcp = ft + (ii * 16) * 128 + n;
            float* fsp = fcp + 8 * 128;
            float twoc = 2.f * c1;
            float cp = 1.f, spv = 0.f, ck = c1, sk = s1;
            fcp[0] = c1; fsp[0] = s1;
#pragma unroll
            for (int k = 1; k < 8; k++) {
                float cn = twoc * ck - cp;
                float sn = twoc * sk - spv;
                cp = ck; spv = sk; ck = cn; sk = sn;
                fcp[k * 128] = ck; fsp[k * 128] = sk;
            }
        }
        {
            const float4* src = reinterpret_cast<const float4*>(Bt + kt * (KT * HID));
            float4* dst = reinterpret_cast<float4*>(ct);
#pragma unroll
            for (int r = 0; r < 8; r++) dst[tid + 128 * r] = src[tid + 128 * r];
        }
        __syncthreads();

#pragma unroll 4
        for (int f = 0; f < KT; f++) {
            const float* ftf = ft + f * 128;
            ull x0 = *reinterpret_cast<const ull*>(ftf + (ng     ) * 2);
            ull x1 = *reinterpret_cast<const ull*>(ftf + (ng + 16) * 2);
            ull x2 = *reinterpret_cast<const ull*>(ftf + (ng + 32) * 2);
            ull x3 = *reinterpret_cast<const ull*>(ftf + (ng + 48) * 2);
            const float* ctf = ct + f * HID + jg * 8;
            float4 cA = *reinterpret_cast<const float4*>(ctf);
            float4 cB = *reinterpret_cast<const float4*>(ctf + 4);
            ull c0 = pk2(cA.x), c1 = pk2(cA.y), c2 = pk2(cA.z), c3 = pk2(cA.w);
            ull c4 = pk2(cB.x), c5 = pk2(cB.y), c6 = pk2(cB.z), c7 = pk2(cB.w);
            fma2(acc[0][0], c0, x0); fma2(acc[0][1], c0, x1); fma2(acc[0][2], c0, x2); fma2(acc[0][3], c0, x3);
            fma2(acc[1][0], c1, x0); fma2(acc[1][1], c1, x1); fma2(acc[1][2], c1, x2); fma2(acc[1][3], c1, x3);
            fma2(acc[2][0], c2, x0); fma2(acc[2][1], c2, x1); fma2(acc[2][2], c2, x2); fma2(acc[2][3], c2, x3);
            fma2(acc[3][0], c3, x0); fma2(acc[3][1], c3, x1); fma2(acc[3][2], c3, x2); fma2(acc[3][3], c3, x3);
            fma2(acc[4][0], c4, x0); fma2(acc[4][1], c4, x1); fma2(acc[4][2], c4, x2); fma2(acc[4][3], c4, x3);
            fma2(acc[5][0], c5, x0); fma2(acc[5][1], c5, x1); fma2(acc[5][2], c5, x2); fma2(acc[5][3], c5, x3);
            fma2(acc[6][0], c6, x0); fma2(acc[6][1], c6, x1); fma2(acc[6][2], c6, x2); fma2(acc[6][3], c6, x3);
            fma2(acc[7][0], c7, x0); fma2(acc[7][1], c7, x1); fma2(acc[7][2], c7, x2); fma2(acc[7][3], c7, x3);
        }
        __syncthreads();
    }

#pragma unroll
    for (int p = 0; p < 4; p++) {
        int node = n0 + (ng + p * 16) * 2;
        float r0[8], r1[8];
#pragma unroll
        for (int jj = 0; jj < 8; jj++) {
            float2 v = up2(acc[jj][p]);
            r0[jj] = v.x; r1[jj] = v.y;
        }
        float4* d0 = reinterpret_cast<float4*>(xout + (size_t)node * HID + jg * 8);
        d0[0] = make_float4(r0[0], r0[1], r0[2], r0[3]);
        d0[1] = make_float4(r0[4], r0[5], r0[6], r0[7]);
        float4* d1 = reinterpret_cast<float4*>(xout + (size_t)(node + 1) * HID + jg * 8);
        d1[0] = make_float4(r1[0], r1[1], r1[2], r1[3]);
        d1[1] = make_float4(r1[4], r1[5], r1[6], r1[7]);
    }
}

// ---------------------------------------------------------------------------
// out = log_softmax(h @ W_out). Warp per node, 8 nodes/CTA, all-SMEM inner loop.
// ---------------------------------------------------------------------------
__global__ __launch_bounds__(256) void out_kernel(
    const float* __restrict__ Wout, float* __restrict__ out)
{
    __shared__ float wsh[HID * OUTF];
    __shared__ float hsh[8][HID];
    const int tid  = threadIdx.x;
    const int nloc = tid >> 5;
    const int n    = blockIdx.x * 8 + nloc;
    const int lane = tid & 31;

    for (int idx = tid; idx < HID * OUTF; idx += 256) wsh[idx] = Wout[idx];
    for (int idx = tid; idx < 8 * HID; idx += 256) {
        int nl = idx >> 6, i = idx & 63;
        hsh[nl][i] = g_bufA[(size_t)(blockIdx.x * 8 + nl) * HID + i];
    }
    __syncthreads();

    float o0 = 0.f, o1 = 0.f;
#pragma unroll 8
    for (int i = 0; i < HID; i++) {
        float hv = hsh[nloc][i];
        o0 += hv * wsh[i * OUTF + lane];
        if (lane < 8) o1 += hv * wsh[i * OUTF + 32 + lane];
    }

    float m = (lane < 8) ? fmaxf(o0, o1) : o0;
#pragma unroll
    for (int off = 16; off; off >>= 1)
        m = fmaxf(m, __shfl_xor_sync(0xFFFFFFFFu, m, off));

    float e = expf(o0 - m) + ((lane < 8) ? expf(o1 - m) : 0.f);
#pragma unroll
    for (int off = 16; off; off >>= 1)
        e += __shfl_xor_sync(0xFFFFFFFFu, e, off);

    float ls = m + logf(e);
    out[(size_t)n * OUTF + lane] = o0 - ls;
    if (lane < 8) out[(size_t)n * OUTF + 32 + lane] = o1 - ls;
}

// ---------------------------------------------------------------------------
extern "C" void kernel_launch(void* const* d_in, const int* in_sizes, int n_in,
                              void* d_out, int out_size)
{
    const float* x     = (const float*)d_in[0];
    const int*   erow  = (const int*)  d_in[1];
    const int*   ecol  = (const int*)  d_in[2];
    const float* ew    = (const float*)d_in[3];
    const float* W_in  = (const float*)d_in[4];
    const float* b_in  = (const float*)d_in[5];
    const float* c1    = (const float*)d_in[6];
    const float* c2    = (const float*)d_in[7];
    const float* W_out = (const float*)d_in[8];
    float* out = (float*)d_out;

    float *bufA = nullptr, *bufB = nullptr, *Bt = nullptr;
    cudaGetSymbolAddress((void**)&bufA, g_bufA);
    cudaGetSymbolAddress((void**)&bufB, g_bufB);
    cudaGetSymbolAddress((void**)&Bt,   g_Bt);

    const int KAN_SMEM = (HID * 129 + KT * 128 + KT * HID) * (int)sizeof(float);
    cudaFuncSetAttribute(kan_kernel,
                         cudaFuncAttributeMaxDynamicSharedMemorySize, KAN_SMEM);

    const int kanBlocks  = NNP / 128;
    const int spmmBlocks = (NN + 7) / 8;

    // CSR build (counters re-armed by zero_cnt at the END of each replay)
    hist_kernel<<<NE / 256, 256>>>(erow);                        // 0
    scanA_kernel<<<NB, 256>>>();                                 // 1
    scanB_kernel<<<NB, 256>>>();                                 // 2
    scatter_kernel<<<NE / 256, 256>>>(erow, ecol, ew);           // 3 (profiled)

    transpose_coeff<<<256, 256>>>(c1, Bt);                       // 4
    transpose_coeff<<<256, 256>>>(c2, Bt + NFT * HID);           // 5
    lin_in_kernel<<<NN / 16, 256>>>(x, W_in, b_in);              // 6

    spmm_csr_kernel<<<spmmBlocks, 256>>>(bufA, bufB);            // 7
    kan_kernel<<<kanBlocks, 128, KAN_SMEM>>>(bufB, Bt, bufA);    // 8
    spmm_csr_kernel<<<spmmBlocks, 256>>>(bufA, bufB);            // 9
    kan_kernel<<<kanBlocks, 128, KAN_SMEM>>>(bufB, Bt + NFT * HID, bufA); // 10
    out_kernel<<<NN / 8, 256>>>(W_out, out);                     // 11

    zero_cnt_kernel<<<(NN + 255) / 256, 256>>>();                // 12 (re-arm)
}

// round 8
// speedup vs baseline: 1.2500x; 1.0278x over previous
#include <cuda_runtime.h>
#include <math.h>

#define NN    100000
#define NNP   100096          // padded to multiple of 128
#define NE    1600000
#define INF   128
#define HID   64
#define OUTF  40
#define GRD   8
#define NFT   1024            // features: f = i*16 + branch*8 + k
#define KT    64              // f per tile
#define KTI   (NFT/KT)        // 16 tiles
#define NB    391             // build grid: ceil(NN/256), all co-resident

typedef unsigned long long ull;

// Scratch (no cudaMalloc; __device__ globals are zero-initialized)
__device__ float g_bufA[(size_t)NNP * HID];
__device__ float g_bufB[(size_t)NNP * HID];
__device__ float g_Bt[2][NFT * HID];   // transposed coeffs: Bt[f*64 + j]
__device__ int   g_rowstart[NN + 1];
__device__ int   g_cnt[NN];            // zeroed in build phase 3 each replay
__device__ int   g_cur[NN];
__device__ int   g_bsum[NB];
__device__ ull   g_edges[NE];          // packed (w<<32 | col), CSR by row
__device__ int   g_gsync;              // grid barrier counter; reset by lin_in

// ---------------- f32x2 helpers ----------------
__device__ __forceinline__ ull pk2(float s) {
    ull d; unsigned u = __float_as_uint(s);
    asm("mov.b64 %0, {%1,%1};" : "=l"(d) : "r"(u));
    return d;
}
__device__ __forceinline__ void fma2(ull& d, ull a, ull b) {
    asm("fma.rn.f32x2 %0, %1, %2, %0;" : "+l"(d) : "l"(a), "l"(b));
}
__device__ __forceinline__ float2 up2(ull v) {
    unsigned lo, hi;
    asm("mov.b64 {%0,%1}, %2;" : "=r"(lo), "=r"(hi) : "l"(v));
    return make_float2(__uint_as_float(lo), __uint_as_float(hi));
}

// ---------------------------------------------------------------------------
// grid barrier for the co-resident build kernel (monotonic counter; reset
// externally by lin_in AFTER this kernel completes, stream-ordered)
// ---------------------------------------------------------------------------
__device__ __forceinline__ void gsync(int target)
{
    __threadfence();
    __syncthreads();
    if (threadIdx.x == 0) {
        atomicAdd(&g_gsync, 1);
        while (atomicAdd(&g_gsync, 0) < target) { }
    }
    __syncthreads();
}

// ---------------------------------------------------------------------------
// Fused CSR build: hist -> scan(local) -> scan(offsets)+init -> scatter+rearm
// 391 CTAs x 256 threads, all co-resident (8 CTAs/SM capacity >> 391/148).
// ---------------------------------------------------------------------------
__global__ __launch_bounds__(256) void build_csr_kernel(
    const int* __restrict__ erow, const int* __restrict__ ecol,
    const float* __restrict__ ew)
{
    __shared__ int sh[256];
    __shared__ int off_sh;
    const int b   = blockIdx.x;
    const int tid = threadIdx.x;
    const int gt  = b * 256 + tid;

    // phase 0: histogram over rows (grid-stride)
    for (int e = gt; e < NE; e += 256 * NB)
        atomicAdd(&g_cnt[erow[e]], 1);
    gsync(NB);

    // phase 1: block-local exclusive scan of counts
    int v = (gt < NN) ? __ldcg(&g_cnt[gt]) : 0;
    sh[tid] = v;
    __syncthreads();
    for (int off = 1; off < 256; off <<= 1) {
        int t = (tid >= off) ? sh[tid - off] : 0;
        __syncthreads();
        if (tid >= off) sh[tid] += t;
        __syncthreads();
    }
    int locpre = sh[tid] - v;                 // exclusive local prefix
    if (tid == 255) g_bsum[b] = sh[255];
    gsync(2 * NB);

    // phase 2: block offsets; init rowstart + cursors
    if (tid == 0) {
        int s = 0;
        for (int j = 0; j < b; j++) s += __ldcg(&g_bsum[j]);
        off_sh = s;
    }
    __syncthreads();
    if (gt < NN) {
        int rs = off_sh + locpre;
        g_rowstart[gt] = rs;
        g_cur[gt]      = rs;
        if (gt == NN - 1) g_rowstart[NN] = rs + v;
    }
    gsync(3 * NB);

    // phase 3: re-arm counters + scatter edges into CSR order
    if (gt < NN) g_cnt[gt] = 0;
    for (int e = gt; e < NE; e += 256 * NB) {
        int r = erow[e];
        unsigned c = (unsigned)ecol[e];
        unsigned w = __float_as_uint(ew[e]);
        int pos = atomicAdd(&g_cur[r], 1);
        g_edges[pos] = ((ull)w << 32) | (ull)c;
    }
}

// ---------------------------------------------------------------------------
// CSR spmm: warp per destination row, lane = 2 features, unroll-8 gather.
// ---------------------------------------------------------------------------
__global__ __launch_bounds__(256) void spmm_csr_kernel(
    const float* __restrict__ xin, float* __restrict__ xout)
{
    const int node = blockIdx.x * 8 + (threadIdx.x >> 5);
    const int lane = threadIdx.x & 31;
    if (node >= NN) return;

    const int s = g_rowstart[node];
    const int e = g_rowstart[node + 1];
    const ull* __restrict__ xin2 = reinterpret_cast<const ull*>(xin);

    ull acc = 0ULL;
    int i = s;
    for (; i + 8 <= e; i += 8) {
        ull p0 = __ldg(g_edges + i + 0), p1 = __ldg(g_edges + i + 1);
        ull p2 = __ldg(g_edges + i + 2), p3 = __ldg(g_edges + i + 3);
        ull p4 = __ldg(g_edges + i + 4), p5 = __ldg(g_edges + i + 5);
        ull p6 = __ldg(g_edges + i + 6), p7 = __ldg(g_edges + i + 7);
        ull v0 = __ldg(xin2 + (size_t)(unsigned)p0 * 32 + lane);
        ull v1 = __ldg(xin2 + (size_t)(unsigned)p1 * 32 + lane);
        ull v2 = __ldg(xin2 + (size_t)(unsigned)p2 * 32 + lane);
        ull v3 = __ldg(xin2 + (size_t)(unsigned)p3 * 32 + lane);
        ull v4 = __ldg(xin2 + (size_t)(unsigned)p4 * 32 + lane);
        ull v5 = __ldg(xin2 + (size_t)(unsigned)p5 * 32 + lane);
        ull v6 = __ldg(xin2 + (size_t)(unsigned)p6 * 32 + lane);
        ull v7 = __ldg(xin2 + (size_t)(unsigned)p7 * 32 + lane);
        fma2(acc, pk2(__uint_as_float((unsigned)(p0 >> 32))), v0);
        fma2(acc, pk2(__uint_as_float((unsigned)(p1 >> 32))), v1);
        fma2(acc, pk2(__uint_as_float((unsigned)(p2 >> 32))), v2);
        fma2(acc, pk2(__uint_as_float((unsigned)(p3 >> 32))), v3);
        fma2(acc, pk2(__uint_as_float((unsigned)(p4 >> 32))), v4);
        fma2(acc, pk2(__uint_as_float((unsigned)(p5 >> 32))), v5);
        fma2(acc, pk2(__uint_as_float((unsigned)(p6 >> 32))), v6);
        fma2(acc, pk2(__uint_as_float((unsigned)(p7 >> 32))), v7);
    }
    for (; i + 2 <= e; i += 2) {
        ull p0 = __ldg(g_edges + i + 0), p1 = __ldg(g_edges + i + 1);
        ull v0 = __ldg(xin2 + (size_t)(unsigned)p0 * 32 + lane);
        ull v1 = __ldg(xin2 + (size_t)(unsigned)p1 * 32 + lane);
        fma2(acc, pk2(__uint_as_float((unsigned)(p0 >> 32))), v0);
        fma2(acc, pk2(__uint_as_float((unsigned)(p1 >> 32))), v1);
    }
    if (i < e) {
        ull p = __ldg(g_edges + i);
        ull v = __ldg(xin2 + (size_t)(unsigned)p * 32 + lane);
        fma2(acc, pk2(__uint_as_float((unsigned)(p >> 32))), v);
    }
    reinterpret_cast<ull*>(xout)[(size_t)node * 32 + lane] = acc;
}

// ---------------------------------------------------------------------------
// Transpose coeff [2][64][64][8] -> Bt[1024][64], f = i*16 + b*8 + k
// ---------------------------------------------------------------------------
__global__ __launch_bounds__(256) void transpose_coeff(
    const float* __restrict__ c, float* __restrict__ Bt)
{
    int idx = blockIdx.x * 256 + threadIdx.x;
    int j = idx & 63;
    int f = idx >> 6;
    int i = f >> 4, b = (f >> 3) & 1, k = f & 7;
    Bt[idx] = c[(((size_t)b * HID + j) * HID + i) * GRD + k];
}

// ---------------------------------------------------------------------------
// h = x @ W_in + b_in -> bufA.  Also resets the build grid-barrier counter.
// ---------------------------------------------------------------------------
__global__ __launch_bounds__(256) void lin_in_kernel(
    const float* __restrict__ x, const float* __restrict__ W,
    const float* __restrict__ b)
{
    if (blockIdx.x == 0 && threadIdx.x == 0) g_gsync = 0;   // re-arm barrier

    __shared__ float xs[16][INF];
    __shared__ float ws[INF * HID];
    const int n0  = blockIdx.x * 16;
    const int tid = threadIdx.x;

    for (int idx = tid; idx < INF * HID / 4; idx += 256)
        reinterpret_cast<float4*>(ws)[idx] =
            reinterpret_cast<const float4*>(W)[idx];
    for (int idx = tid; idx < 16 * INF; idx += 256) {
        int n = idx >> 7, c = idx & 127;
        xs[n][c] = x[(size_t)(n0 + n) * INF + c];
    }
    __syncthreads();

    const int j4 = (tid & 15) * 4;
    const int ny = tid >> 4;
    const int n  = n0 + ny;

    ull a01 = 0ULL, a23 = 0ULL;
#pragma unroll 8
    for (int i = 0; i < INF; i++) {
        ull xv = pk2(xs[ny][i]);
        const ull* w2 = reinterpret_cast<const ull*>(ws + i * HID + j4);
        fma2(a01, xv, w2[0]);
        fma2(a23, xv, w2[1]);
    }
    float2 v01 = up2(a01), v23 = up2(a23);
    *reinterpret_cast<float4*>(g_bufA + (size_t)n * HID + j4) =
        make_float4(v01.x + b[j4], v01.y + b[j4 + 1],
                    v23.x + b[j4 + 2], v23.y + b[j4 + 3]);
}

// ---------------------------------------------------------------------------
// Fourier KAN as SMEM-tiled GEMM with f32x2 packed math. __sincosf for trig.
// ---------------------------------------------------------------------------
__global__ __launch_bounds__(128) void kan_kernel(
    const float* __restrict__ xin, const float* __restrict__ Bt,
    float* __restrict__ xout)
{
    extern __shared__ float sm[];
    float* sx = sm;                       // 64*129
    float* ft = sx + HID * 129;           // 64*128
    float* ct = ft + KT * 128;            // 64*64

    const int tid = threadIdx.x;
    const int n0  = blockIdx.x * 128;
    const int ng  = tid & 15;
    const int jg  = tid >> 4;

#pragma unroll
    for (int r = 0; r < 64; r++) {
        int idx = r * 128 + tid;
        int i = idx & 63;
        int n = idx >> 6;
        sx[i * 129 + n] = xin[(size_t)(n0 + n) * HID + i];
    }
    __syncthreads();

    ull acc[8][4];
#pragma unroll
    for (int jj = 0; jj < 8; jj++)
#pragma unroll
        for (int p = 0; p < 4; p++) acc[jj][p] = 0ULL;

    for (int kt = 0; kt < KTI; kt++) {
#pragma unroll
        for (int r = 0; r < 4; r++) {
            int idx = tid + 128 * r;
            int n  = idx & 127;
            int ii = idx >> 7;
            float xv = sx[(kt * 4 + ii) * 129 + n];
            float s1, c1;
            __sincosf(xv, &s1, &c1);
            float* fcp = ft + (ii * 16) * 128 + n;
            float* fsp = fcp + 8 * 128;
            float twoc = 2.f * c1;
            float cp = 1.f, spv = 0.f, ck = c1, sk = s1;
            fcp[0] = c1; fsp[0] = s1;
#pragma unroll
            for (int k = 1; k < 8; k++) {
                float cn = twoc * ck - cp;
                float sn = twoc * sk - spv;
                cp = ck; spv = sk; ck = cn; sk = sn;
                fcp[k * 128] = ck; fsp[k * 128] = sk;
            }
        }
        {
            const float4* src = reinterpret_cast<const float4*>(Bt + kt * (KT * HID));
            float4* dst = reinterpret_cast<float4*>(ct);
#pragma unroll
            for (int r = 0; r < 8; r++) dst[tid + 128 * r] = src[tid + 128 * r];
        }
        __syncthreads();

#pragma unroll 4
        for (int f = 0; f < KT; f++) {
            const float* ftf = ft + f * 128;
            ull x0 = *reinterpret_cast<const ull*>(ftf + (ng     ) * 2);
            ull x1 = *reinterpret_cast<const ull*>(ftf + (ng + 16) * 2);
            ull x2 = *reinterpret_cast<const ull*>(ftf + (ng + 32) * 2);
            ull x3 = *reinterpret_cast<const ull*>(ftf + (ng + 48) * 2);
            const float* ctf = ct + f * HID + jg * 8;
            float4 cA = *reinterpret_cast<const float4*>(ctf);
            float4 cB = *reinterpret_cast<const float4*>(ctf + 4);
            ull c0 = pk2(cA.x), c1 = pk2(cA.y), c2 = pk2(cA.z), c3 = pk2(cA.w);
            ull c4 = pk2(cB.x), c5 = pk2(cB.y), c6 = pk2(cB.z), c7 = pk2(cB.w);
            fma2(acc[0][0], c0, x0); fma2(acc[0][1], c0, x1); fma2(acc[0][2], c0, x2); fma2(acc[0][3], c0, x3);
            fma2(acc[1][0], c1, x0); fma2(acc[1][1], c1, x1); fma2(acc[1][2], c1, x2); fma2(acc[1][3], c1, x3);
            fma2(acc[2][0], c2, x0); fma2(acc[2][1], c2, x1); fma2(acc[2][2], c2, x2); fma2(acc[2][3], c2, x3);
            fma2(acc[3][0], c3, x0); fma2(acc[3][1], c3, x1); fma2(acc[3][2], c3, x2); fma2(acc[3][3], c3, x3);
            fma2(acc[4][0], c4, x0); fma2(acc[4][1], c4, x1); fma2(acc[4][2], c4, x2); fma2(acc[4][3], c4, x3);
            fma2(acc[5][0], c5, x0); fma2(acc[5][1], c5, x1); fma2(acc[5][2], c5, x2); fma2(acc[5][3], c5, x3);
            fma2(acc[6][0], c6, x0); fma2(acc[6][1], c6, x1); fma2(acc[6][2], c6, x2); fma2(acc[6][3], c6, x3);
            fma2(acc[7][0], c7, x0); fma2(acc[7][1], c7, x1); fma2(acc[7][2], c7, x2); fma2(acc[7][3], c7, x3);
        }
        __syncthreads();
    }

#pragma unroll
    for (int p = 0; p < 4; p++) {
        int node = n0 + (ng + p * 16) * 2;
        float r0[8], r1[8];
#pragma unroll
        for (int jj = 0; jj < 8; jj++) {
            float2 v = up2(acc[jj][p]);
            r0[jj] = v.x; r1[jj] = v.y;
        }
        float4* d0 = reinterpret_cast<float4*>(xout + (size_t)node * HID + jg * 8);
        d0[0] = make_float4(r0[0], r0[1], r0[2], r0[3]);
        d0[1] = make_float4(r0[4], r0[5], r0[6], r0[7]);
        float4* d1 = reinterpret_cast<float4*>(xout + (size_t)(node + 1) * HID + jg * 8);
        d1[0] = make_float4(r1[0], r1[1], r1[2], r1[3]);
        d1[1] = make_float4(r1[4], r1[5], r1[6], r1[7]);
    }
}

// ---------------------------------------------------------------------------
// out = log_softmax(h @ W_out). Warp per node, 8 nodes/CTA, all-SMEM inner loop.
// ---------------------------------------------------------------------------
__global__ __launch_bounds__(256) void out_kernel(
    const float* __restrict__ Wout, float* __restrict__ out)
{
    __shared__ float wsh[HID * OUTF];
    __shared__ float hsh[8][HID];
    const int tid  = threadIdx.x;
    const int nloc = tid >> 5;
    const int n    = blockIdx.x * 8 + nloc;
    const int lane = tid & 31;

    for (int idx = tid; idx < HID * OUTF; idx += 256) wsh[idx] = Wout[idx];
    for (int idx = tid; idx < 8 * HID; idx += 256) {
        int nl = idx >> 6, i = idx & 63;
        hsh[nl][i] = g_bufA[(size_t)(blockIdx.x * 8 + nl) * HID + i];
    }
    __syncthreads();

    float o0 = 0.f, o1 = 0.f;
#pragma unroll 8
    for (int i = 0; i < HID; i++) {
        float hv = hsh[nloc][i];
        o0 += hv * wsh[i * OUTF + lane];
        if (lane < 8) o1 += hv * wsh[i * OUTF + 32 + lane];
    }

    float m = (lane < 8) ? fmaxf(o0, o1) : o0;
#pragma unroll
    for (int off = 16; off; off >>= 1)
        m = fmaxf(m, __shfl_xor_sync(0xFFFFFFFFu, m, off));

    float e = expf(o0 - m) + ((lane < 8) ? expf(o1 - m) : 0.f);
#pragma unroll
    for (int off = 16; off; off >>= 1)
        e += __shfl_xor_sync(0xFFFFFFFFu, e, off);

    float ls = m + logf(e);
    out[(size_t)n * OUTF + lane] = o0 - ls;
    if (lane < 8) out[(size_t)n * OUTF + 32 + lane] = o1 - ls;
}

// ---------------------------------------------------------------------------
extern "C" void kernel_launch(void* const* d_in, const int* in_sizes, int n_in,
                              void* d_out, int out_size)
{
    const float* x     = (const float*)d_in[0];
    const int*   erow  = (const int*)  d_in[1];
    const int*   ecol  = (const int*)  d_in[2];
    const float* ew    = (const float*)d_in[3];
    const float* W_in  = (const float*)d_in[4];
    const float* b_in  = (const float*)d_in[5];
    const float* c1    = (const float*)d_in[6];
    const float* c2    = (const float*)d_in[7];
    const float* W_out = (const float*)d_in[8];
    float* out = (float*)d_out;

    float *bufA = nullptr, *bufB = nullptr, *Bt = nullptr;
    cudaGetSymbolAddress((void**)&bufA, g_bufA);
    cudaGetSymbolAddress((void**)&bufB, g_bufB);
    cudaGetSymbolAddress((void**)&Bt,   g_Bt);

    const int KAN_SMEM = (HID * 129 + KT * 128 + KT * HID) * (int)sizeof(float);
    cudaFuncSetAttribute(kan_kernel,
                         cudaFuncAttributeMaxDynamicSharedMemorySize, KAN_SMEM);

    const int kanBlocks  = NNP / 128;
    const int spmmBlocks = (NN + 7) / 8;

    build_csr_kernel<<<NB, 256>>>(erow, ecol, ew);                // 0
    lin_in_kernel<<<NN / 16, 256>>>(x, W_in, b_in);               // 1 (+barrier reset)
    transpose_coeff<<<256, 256>>>(c1, Bt);                        // 2
    spmm_csr_kernel<<<spmmBlocks, 256>>>(bufA, bufB);             // 3  <-- profiled
    kan_kernel<<<kanBlocks, 128, KAN_SMEM>>>(bufB, Bt, bufA);     // 4
    spmm_csr_kernel<<<spmmBlocks, 256>>>(bufA, bufB);             // 5
    transpose_coeff<<<256, 256>>>(c2, Bt + NFT * HID);            // 6
    kan_kernel<<<kanBlocks, 128, KAN_SMEM>>>(bufB, Bt + NFT * HID, bufA); // 7
    out_kernel<<<NN / 8, 256>>>(W_out, out);                      // 8
}

// round 9
// speedup vs baseline: 2.0654x; 1.6523x over previous
#include <cuda_runtime.h>
#include <cuda_bf16.h>
#include <math.h>
#include <stdint.h>

#define NN    100000
#define NNP   100096          // padded to multiple of 128
#define NE    1600000
#define INF   128
#define HID   64
#define OUTF  40
#define GRD   8
#define NB    391             // build grid: ceil(NN/256), all co-resident

typedef unsigned long long ull;

// ------------------------- scratch (no cudaMalloc) -------------------------
__device__ float g_bufA[(size_t)NNP * HID];
__device__ float g_bufB[(size_t)NNP * HID];
__device__ int   g_rowstart[NN + 1];
__device__ int   g_cnt[NN];            // zeroed in build phase 3 each replay
__device__ int   g_cur[NN];
__device__ int   g_bsum[NB];
__device__ ull   g_edges[NE];          // packed (w<<32 | col), CSR by row
__device__ int   g_gsync;              // grid barrier counter; reset by lin_in
// bf16 hi/lo split coeffs: [layer][tile 0..15][j 0..63][kk 0..63]
__device__ __nv_bfloat16 g_Ch[2][16 * 64 * 64];
__device__ __nv_bfloat16 g_Cl[2][16 * 64 * 64];

// ---------------- f32x2 helpers (spmm / lin_in) ----------------
__device__ __forceinline__ ull pk2(float s) {
    ull d; unsigned u = __float_as_uint(s);
    asm("mov.b64 %0, {%1,%1};" : "=l"(d) : "r"(u));
    return d;
}
__device__ __forceinline__ void fma2(ull& d, ull a, ull b) {
    asm("fma.rn.f32x2 %0, %1, %2, %0;" : "+l"(d) : "l"(a), "l"(b));
}
__device__ __forceinline__ float2 up2(ull v) {
    unsigned lo, hi;
    asm("mov.b64 {%0,%1}, %2;" : "=r"(lo), "=r"(hi) : "l"(v));
    return make_float2(__uint_as_float(lo), __uint_as_float(hi));
}

// ---------------- mma helpers (baseline sm_80+ ISA, no 'a' features) -------
__device__ __forceinline__ uint32_t smem_u32(const void* p) {
    uint32_t a;
    asm("{ .reg .u64 t; cvta.to.shared.u64 t, %1; cvt.u32.u64 %0, t; }"
        : "=r"(a) : "l"(p));
    return a;
}
__device__ __forceinline__ void ldsm4(uint32_t (&r)[4], uint32_t addr) {
    asm volatile("ldmatrix.sync.aligned.m8n8.x4.shared.b16 {%0,%1,%2,%3}, [%4];"
                 : "=r"(r[0]), "=r"(r[1]), "=r"(r[2]), "=r"(r[3]) : "r"(addr));
}
__device__ __forceinline__ void mma16816(float (&d)[4], const uint32_t (&a)[4],
                                         uint32_t b0, uint32_t b1) {
    asm volatile("mma.sync.aligned.m16n8k16.row.col.f32.bf16.bf16.f32 "
                 "{%0,%1,%2,%3}, {%4,%5,%6,%7}, {%8,%9}, {%0,%1,%2,%3};"
                 : "+f"(d[0]), "+f"(d[1]), "+f"(d[2]), "+f"(d[3])
                 : "r"(a[0]), "r"(a[1]), "r"(a[2]), "r"(a[3]),
                   "r"(b0), "r"(b1));
}

// ---------------------------------------------------------------------------
// grid barrier for the co-resident build kernel
// ---------------------------------------------------------------------------
__device__ __forceinline__ void gsync(int target)
{
    __threadfence();
    __syncthreads();
    if (threadIdx.x == 0) {
        atomicAdd(&g_gsync, 1);
        while (atomicAdd(&g_gsync, 0) < target) { }
    }
    __syncthreads();
}

// ---------------------------------------------------------------------------
// Fused CSR build + coeff bf16 hi/lo prep
// ---------------------------------------------------------------------------
__global__ __launch_bounds__(256) void build_csr_kernel(
    const int* __restrict__ erow, const int* __restrict__ ecol,
    const float* __restrict__ ew,
    const float* __restrict__ c1, const float* __restrict__ c2)
{
    __shared__ int sh[256];
    __shared__ int off_sh;
    const int b   = blockIdx.x;
    const int tid = threadIdx.x;
    const int gt  = b * 256 + tid;

    // phase 0a: coeff split -> bf16 hi/lo tiles
    for (int idx = gt; idx < 2 * 64 * 1024; idx += 256 * NB) {
        int L   = idx >> 16;
        int rem = idx & 65535;
        int j   = rem >> 10;
        int f   = rem & 1023;
        const float* cf = L ? c2 : c1;
        int i = f >> 4, br = (f >> 3) & 1, k = f & 7;
        float v = cf[(((size_t)br * HID + j) * HID + i) * GRD + k];
        __nv_bfloat16 vh = __float2bfloat16(v);
        __nv_bfloat16 vl = __float2bfloat16(v - __bfloat162float(vh));
        int t = f >> 6, kk = f & 63;
        g_Ch[L][(t * 64 + j) * 64 + kk] = vh;
        g_Cl[L][(t * 64 + j) * 64 + kk] = vl;
    }

    // phase 0b: histogram over rows (grid-stride)
    for (int e = gt; e < NE; e += 256 * NB)
        atomicAdd(&g_cnt[erow[e]], 1);
    gsync(NB);

    // phase 1: block-local exclusive scan of counts
    int v = (gt < NN) ? __ldcg(&g_cnt[gt]) : 0;
    sh[tid] = v;
    __syncthreads();
    for (int off = 1; off < 256; off <<= 1) {
        int t = (tid >= off) ? sh[tid - off] : 0;
        __syncthreads();
        if (tid >= off) sh[tid] += t;
        __syncthreads();
    }
    int locpre = sh[tid] - v;
    if (tid == 255) g_bsum[b] = sh[255];
    gsync(2 * NB);

    // phase 2: block offsets; init rowstart + cursors
    if (tid == 0) {
        int s = 0;
        for (int j = 0; j < b; j++) s += __ldcg(&g_bsum[j]);
        off_sh = s;
    }
    __syncthreads();
    if (gt < NN) {
        int rs = off_sh + locpre;
        g_rowstart[gt] = rs;
        g_cur[gt]      = rs;
        if (gt == NN - 1) g_rowstart[NN] = rs + v;
    }
    gsync(3 * NB);

    // phase 3: re-arm counters + scatter edges
    if (gt < NN) g_cnt[gt] = 0;
    for (int e = gt; e < NE; e += 256 * NB) {
        int r = erow[e];
        unsigned c = (unsigned)ecol[e];
        unsigned w = __float_as_uint(ew[e]);
        int pos = atomicAdd(&g_cur[r], 1);
        g_edges[pos] = ((ull)w << 32) | (ull)c;
    }
}

// ---------------------------------------------------------------------------
// CSR spmm: warp per destination row, lane = 2 features, unroll-8 gather.
// ---------------------------------------------------------------------------
__global__ __launch_bounds__(256) void spmm_csr_kernel(
    const float* __restrict__ xin, float* __restrict__ xout)
{
    const int node = blockIdx.x * 8 + (threadIdx.x >> 5);
    const int lane = threadIdx.x & 31;
    if (node >= NN) return;

    const int s = g_rowstart[node];
    const int e = g_rowstart[node + 1];
    const ull* __restrict__ xin2 = reinterpret_cast<const ull*>(xin);

    ull acc = 0ULL;
    int i = s;
    for (; i + 8 <= e; i += 8) {
        ull p0 = __ldg(g_edges + i + 0), p1 = __ldg(g_edges + i + 1);
        ull p2 = __ldg(g_edges + i + 2), p3 = __ldg(g_edges + i + 3);
        ull p4 = __ldg(g_edges + i + 4), p5 = __ldg(g_edges + i + 5);
        ull p6 = __ldg(g_edges + i + 6), p7 = __ldg(g_edges + i + 7);
        ull v0 = __ldg(xin2 + (size_t)(unsigned)p0 * 32 + lane);
        ull v1 = __ldg(xin2 + (size_t)(unsigned)p1 * 32 + lane);
        ull v2 = __ldg(xin2 + (size_t)(unsigned)p2 * 32 + lane);
        ull v3 = __ldg(xin2 + (size_t)(unsigned)p3 * 32 + lane);
        ull v4 = __ldg(xin2 + (size_t)(unsigned)p4 * 32 + lane);
        ull v5 = __ldg(xin2 + (size_t)(unsigned)p5 * 32 + lane);
        ull v6 = __ldg(xin2 + (size_t)(unsigned)p6 * 32 + lane);
        ull v7 = __ldg(xin2 + (size_t)(unsigned)p7 * 32 + lane);
        fma2(acc, pk2(__uint_as_float((unsigned)(p0 >> 32))), v0);
        fma2(acc, pk2(__uint_as_float((unsigned)(p1 >> 32))), v1);
        fma2(acc, pk2(__uint_as_float((unsigned)(p2 >> 32))), v2);
        fma2(acc, pk2(__uint_as_float((unsigned)(p3 >> 32))), v3);
        fma2(acc, pk2(__uint_as_float((unsigned)(p4 >> 32))), v4);
        fma2(acc, pk2(__uint_as_float((unsigned)(p5 >> 32))), v5);
        fma2(acc, pk2(__uint_as_float((unsigned)(p6 >> 32))), v6);
        fma2(acc, pk2(__uint_as_float((unsigned)(p7 >> 32))), v7);
    }
    for (; i + 2 <= e; i += 2) {
        ull p0 = __ldg(g_edges + i + 0), p1 = __ldg(g_edges + i + 1);
        ull v0 = __ldg(xin2 + (size_t)(unsigned)p0 * 32 + lane);
        ull v1 = __ldg(xin2 + (size_t)(unsigned)p1 * 32 + lane);
        fma2(acc, pk2(__uint_as_float((unsigned)(p0 >> 32))), v0);
        fma2(acc, pk2(__uint_as_float((unsigned)(p1 >> 32))), v1);
    }
    if (i < e) {
        ull p = __ldg(g_edges + i);
        ull v = __ldg(xin2 + (size_t)(unsigned)p * 32 + lane);
        fma2(acc, pk2(__uint_as_float((unsigned)(p >> 32))), v);
    }
    reinterpret_cast<ull*>(xout)[(size_t)node * 32 + lane] = acc;
}

// ---------------------------------------------------------------------------
// h = x @ W_in + b_in -> bufA.  Also resets the build grid-barrier counter.
// ---------------------------------------------------------------------------
__global__ __launch_bounds__(256) void lin_in_kernel(
    const float* __restrict__ x, const float* __restrict__ W,
    const float* __restrict__ b)
{
    if (blockIdx.x == 0 && threadIdx.x == 0) g_gsync = 0;

    __shared__ float xs[16][INF];
    __shared__ float ws[INF * HID];
    const int n0  = blockIdx.x * 16;
    const int tid = threadIdx.x;

    for (int idx = tid; idx < INF * HID / 4; idx += 256)
        reinterpret_cast<float4*>(ws)[idx] =
            reinterpret_cast<const float4*>(W)[idx];
    for (int idx = tid; idx < 16 * INF; idx += 256) {
        int n = idx >> 7, c = idx & 127;
        xs[n][c] = x[(size_t)(n0 + n) * INF + c];
    }
    __syncthreads();

    const int j4 = (tid & 15) * 4;
    const int ny = tid >> 4;
    const int n  = n0 + ny;

    ull a01 = 0ULL, a23 = 0ULL;
#pragma unroll 8
    for (int i = 0; i < INF; i++) {
        ull xv = pk2(xs[ny][i]);
        const ull* w2 = reinterpret_cast<const ull*>(ws + i * HID + j4);
        fma2(a01, xv, w2[0]);
        fma2(a23, xv, w2[1]);
    }
    float2 v01 = up2(a01), v23 = up2(a23);
    *reinterpret_cast<float4*>(g_bufA + (size_t)n * HID + j4) =
        make_float4(v01.x + b[j4], v01.y + b[j4 + 1],
                    v23.x + b[j4 + 2], v23.y + b[j4 + 3]);
}

// ---------------------------------------------------------------------------
// KAN layer on tensor cores (mma.sync m16n8k16 bf16, 3-pass hi/lo split).
// CTA: 128 nodes x 64 j, 256 threads = 8 warps (4 M x 2 N), warp tile 32x32.
// K = 1024 features in 16 tiles of 64. SMEM pitch 72 bf16 (144B) for
// conflict-free ldmatrix.
// ---------------------------------------------------------------------------
#define SX_OFF  0
#define FH_OFF  33024
#define FL_OFF  51456
#define CHS_OFF 69888
#define CLS_OFF 79104
#define KAN_SMEM 88320

__global__ __launch_bounds__(256) void kan_mma_kernel(
    const float* __restrict__ xin,
    const __nv_bfloat16* __restrict__ Ch,
    const __nv_bfloat16* __restrict__ Cl,
    float* __restrict__ xout)
{
    extern __shared__ char sm[];
    float*          sx = reinterpret_cast<float*>(sm + SX_OFF);   // [64][129]
    __nv_bfloat16*  fh = reinterpret_cast<__nv_bfloat16*>(sm + FH_OFF); // [128][72]
    __nv_bfloat16*  fl = reinterpret_cast<__nv_bfloat16*>(sm + FL_OFF);
    __nv_bfloat16*  ch = reinterpret_cast<__nv_bfloat16*>(sm + CHS_OFF); // [64][72]
    __nv_bfloat16*  cl = reinterpret_cast<__nv_bfloat16*>(sm + CLS_OFF);

    const int tid   = threadIdx.x;
    const int lane  = tid & 31;
    const int wid   = tid >> 5;
    const int warpM = wid & 3;             // M offset = warpM*32
    const int warpN = wid >> 2;            // N offset = warpN*32
    const int n0    = blockIdx.x * 128;
    const uint32_t sbase = smem_u32(sm);

    // stage inputs transposed: sx[i*129 + n]
#pragma unroll
    for (int r = 0; r < 32; r++) {
        int idx = r * 256 + tid;
        int n = idx >> 6, i = idx & 63;
        sx[i * 129 + n] = xin[(size_t)(n0 + n) * HID + i];
    }
    __syncthreads();

    float acc[2][4][4];
#pragma unroll
    for (int m = 0; m < 2; m++)
#pragma unroll
        for (int nt = 0; nt < 4; nt++)
#pragma unroll
            for (int q = 0; q < 4; q++) acc[m][nt][q] = 0.f;

    const int sel  = lane >> 3;            // ldmatrix address group
    const int lrow = lane & 7;

    for (int t = 0; t < 16; t++) {
        // ---- features: 512 (n, ii) pairs -> bf16 hi/lo into fh/fl ----
#pragma unroll
        for (int r = 0; r < 2; r++) {
            int idx = tid + 256 * r;
            int n  = idx & 127;
            int ii = idx >> 7;             // 0..3
            float xv = sx[(t * 4 + ii) * 129 + n];
            float s1, c1;
            __sincosf(xv, &s1, &c1);
            float cc[8], ss[8];
            cc[0] = c1; ss[0] = s1;
            float twoc = 2.f * c1;
            float cm2 = 1.f, cm1 = c1, sm2 = 0.f, sm1 = s1;
#pragma unroll
            for (int k = 1; k < 8; k++) {
                float cn = twoc * cm1 - cm2;
                float sn = twoc * sm1 - sm2;
                cc[k] = cn; ss[k] = sn;
                cm2 = cm1; cm1 = cn; sm2 = sm1; sm1 = sn;
            }
            int base = n * 72 + ii * 16;
#pragma unroll
            for (int m = 0; m < 4; m++) {
                float a = cc[2 * m], b = cc[2 * m + 1];
                __nv_bfloat162 h2 = __floats2bfloat162_rn(a, b);
                __nv_bfloat162 l2 = __floats2bfloat162_rn(
                    a - __bfloat162float(h2.x), b - __bfloat162float(h2.y));
                *reinterpret_cast<uint32_t*>(fh + base + 2 * m) =
                    *reinterpret_cast<uint32_t*>(&h2);
                *reinterpret_cast<uint32_t*>(fl + base + 2 * m) =
                    *reinterpret_cast<uint32_t*>(&l2);
                a = ss[2 * m]; b = ss[2 * m + 1];
                h2 = __floats2bfloat162_rn(a, b);
                l2 = __floats2bfloat162_rn(
                    a - __bfloat162float(h2.x), b - __bfloat162float(h2.y));
                *reinterpret_cast<uint32_t*>(fh + base + 8 + 2 * m) =
                    *reinterpret_cast<uint32_t*>(&h2);
                *reinterpret_cast<uint32_t*>(fl + base + 8 + 2 * m) =
                    *reinterpret_cast<uint32_t*>(&l2);
            }
        }
        // ---- coeff tile: [64 j][64 kk] -> pitch-72 smem ----
        {
            const uint4* gh = reinterpret_cast<const uint4*>(Ch + t * 4096);
            const uint4* gl = reinterpret_cast<const uint4*>(Cl + t * 4096);
#pragma unroll
            for (int r = 0; r < 2; r++) {
                int q = tid + 256 * r;     // q = j*8 + kk8
                int j = q >> 3, kk8 = q & 7;
                *reinterpret_cast<uint4*>(
                    reinterpret_cast<char*>(ch) + j * 144 + kk8 * 16) = gh[q];
                *reinterpret_cast<uint4*>(
                    reinterpret_cast<char*>(cl) + j * 144 + kk8 * 16) = gl[q];
            }
        }
        __syncthreads();

        // ---- mma over 4 k-steps of 16 ----
#pragma unroll
        for (int ks = 0; ks < 4; ks++) {
            const uint32_t kc2 = ks * 32;  // byte offset of k-column
            uint32_t ah[2][4], al[2][4], bh[2][4], bl[2][4];
#pragma unroll
            for (int m = 0; m < 2; m++) {
                uint32_t ra = FH_OFF +
                    (uint32_t)(warpM * 32 + m * 16 + lrow + (sel & 1) * 8) * 144
                    + kc2 + (uint32_t)(sel >> 1) * 16;
                ldsm4(ah[m], sbase + ra);
                ldsm4(al[m], sbase + ra + (FL_OFF - FH_OFF));
            }
#pragma unroll
            for (int pi = 0; pi < 2; pi++) {
                uint32_t rb = CHS_OFF +
                    (uint32_t)(warpN * 32 + pi * 16 + lrow + (sel >> 1) * 8) * 144
                    + kc2 + (uint32_t)(sel & 1) * 16;
                ldsm4(bh[pi], sbase + rb);
                ldsm4(bl[pi], sbase + rb + (CLS_OFF - CHS_OFF));
            }
#pragma unroll
            for (int m = 0; m < 2; m++) {
#pragma unroll
                for (int nt = 0; nt < 4; nt++) {
                    uint32_t b0h = bh[nt >> 1][(nt & 1) * 2];
                    uint32_t b1h = bh[nt >> 1][(nt & 1) * 2 + 1];
                    uint32_t b0l = bl[nt >> 1][(nt & 1) * 2];
                    uint32_t b1l = bl[nt >> 1][(nt & 1) * 2 + 1];
                    mma16816(acc[m][nt], ah[m], b0h, b1h);
                    mma16816(acc[m][nt], al[m], b0h, b1h);
                    mma16816(acc[m][nt], ah[m], b0l, b1l);
                }
            }
        }
        __syncthreads();
    }

    // ---- epilogue: fragment -> global ----
    const int g = lane >> 2, c = lane & 3;
#pragma unroll
    for (int m = 0; m < 2; m++) {
#pragma unroll
        for (int nt = 0; nt < 4; nt++) {
            int row0 = n0 + warpM * 32 + m * 16 + g;
            int col  = warpN * 32 + nt * 8 + c * 2;
            *reinterpret_cast<float2*>(xout + (size_t)row0 * HID + col) =
                make_float2(acc[m][nt][0], acc[m][nt][1]);
            *reinterpret_cast<float2*>(xout + (size_t)(row0 + 8) * HID + col) =
                make_float2(acc[m][nt][2], acc[m][nt][3]);
        }
    }
}

// ---------------------------------------------------------------------------
// out = log_softmax(h @ W_out). Warp per node, 8 nodes/CTA, all-SMEM inner loop.
// ---------------------------------------------------------------------------
__global__ __launch_bounds__(256) void out_kernel(
    const float* __restrict__ Wout, float* __restrict__ out)
{
    __shared__ float wsh[HID * OUTF];
    __shared__ float hsh[8][HID];
    const int tid  = threadIdx.x;
    const int nloc = tid >> 5;
    const int n    = blockIdx.x * 8 + nloc;
    const int lane = tid & 31;

    for (int idx = tid; idx < HID * OUTF; idx += 256) wsh[idx] = Wout[idx];
    for (int idx = tid; idx < 8 * HID; idx += 256) {
        int nl = idx >> 6, i = idx & 63;
        hsh[nl][i] = g_bufA[(size_t)(blockIdx.x * 8 + nl) * HID + i];
    }
    __syncthreads();

    float o0 = 0.f, o1 = 0.f;
#pragma unroll 8
    for (int i = 0; i < HID; i++) {
        float hv = hsh[nloc][i];
        o0 += hv * wsh[i * OUTF + lane];
        if (lane < 8) o1 += hv * wsh[i * OUTF + 32 + lane];
    }

    float m = (lane < 8) ? fmaxf(o0, o1) : o0;
#pragma unroll
    for (int off = 16; off; off >>= 1)
        m = fmaxf(m, __shfl_xor_sync(0xFFFFFFFFu, m, off));

    float e = expf(o0 - m) + ((lane < 8) ? expf(o1 - m) : 0.f);
#pragma unroll
    for (int off = 16; off; off >>= 1)
        e += __shfl_xor_sync(0xFFFFFFFFu, e, off);

    float ls = m + logf(e);
    out[(size_t)n * OUTF + lane] = o0 - ls;
    if (lane < 8) out[(size_t)n * OUTF + 32 + lane] = o1 - ls;
}

// ---------------------------------------------------------------------------
extern "C" void kernel_launch(void* const* d_in, const int* in_sizes, int n_in,
                              void* d_out, int out_size)
{
    const float* x     = (const float*)d_in[0];
    const int*   erow  = (const int*)  d_in[1];
    const int*   ecol  = (const int*)  d_in[2];
    const float* ew    = (const float*)d_in[3];
    const float* W_in  = (const float*)d_in[4];
    const float* b_in  = (const float*)d_in[5];
    const float* c1    = (const float*)d_in[6];
    const float* c2    = (const float*)d_in[7];
    const float* W_out = (const float*)d_in[8];
    float* out = (float*)d_out;

    float *bufA = nullptr, *bufB = nullptr;
    __nv_bfloat16 *chp = nullptr, *clp = nullptr;
    cudaGetSymbolAddress((void**)&bufA, g_bufA);
    cudaGetSymbolAddress((void**)&bufB, g_bufB);
    cudaGetSymbolAddress((void**)&chp,  g_Ch);
    cudaGetSymbolAddress((void**)&clp,  g_Cl);

    cudaFuncSetAttribute(kan_mma_kernel,
                         cudaFuncAttributeMaxDynamicSharedMemorySize, KAN_SMEM);

    const int kanBlocks  = NNP / 128;          // 782
    const int spmmBlocks = (NN + 7) / 8;
    const size_t cl_sz   = (size_t)16 * 64 * 64;   // bf16 per layer

    build_csr_kernel<<<NB, 256>>>(erow, ecol, ew, c1, c2);              // 0
    lin_in_kernel<<<NN / 16, 256>>>(x, W_in, b_in);                     // 1
    spmm_csr_kernel<<<spmmBlocks, 256>>>(bufA, bufB);                   // 2
    kan_mma_kernel<<<kanBlocks, 256, KAN_SMEM>>>(bufB, chp, clp, bufA); // 3 <- profiled
    spmm_csr_kernel<<<spmmBlocks, 256>>>(bufA, bufB);                   // 4
    kan_mma_kernel<<<kanBlocks, 256, KAN_SMEM>>>(bufB, chp + cl_sz,
                                                 clp + cl_sz, bufA);    // 5
    out_kernel<<<NN / 8, 256>>>(W_out, out);                            // 6
}

// round 10
// speedup vs baseline: 2.1826x; 1.0568x over previous
#include <cuda_runtime.h>
#include <cuda_bf16.h>
#include <math.h>
#include <stdint.h>

#define NN    100000
#define NNP   100096          // padded to multiple of 128
#define NE    1600000
#define INF   128
#define HID   64
#define OUTF  40
#define GRD   8
#define NB    391             // build grid: ceil(NN/256), all co-resident

typedef unsigned long long ull;

// ------------------------- scratch (no cudaMalloc) -------------------------
__device__ float g_bufA[(size_t)NNP * HID];
__device__ float g_bufB[(size_t)NNP * HID];
__device__ int   g_rowstart[NN + 1];
__device__ int   g_cnt[NN];            // zeroed in build phase 3 each replay
__device__ int   g_cur[NN];
__device__ int   g_bsum[NB];
__device__ ull   g_edges[NE];          // packed (w<<32 | col), CSR by row
__device__ int   g_gsync;              // grid barrier counter; reset by lin_in
// bf16 hi/lo split coeffs: [layer][tile 0..15][j 0..63][kk 0..63]
__device__ __nv_bfloat16 g_Ch[2][16 * 64 * 64];
__device__ __nv_bfloat16 g_Cl[2][16 * 64 * 64];

// ---------------- f32x2 helpers (spmm / lin_in) ----------------
__device__ __forceinline__ ull pk2(float s) {
    ull d; unsigned u = __float_as_uint(s);
    asm("mov.b64 %0, {%1,%1};" : "=l"(d) : "r"(u));
    return d;
}
__device__ __forceinline__ void fma2(ull& d, ull a, ull b) {
    asm("fma.rn.f32x2 %0, %1, %2, %0;" : "+l"(d) : "l"(a), "l"(b));
}
__device__ __forceinline__ float2 up2(ull v) {
    unsigned lo, hi;
    asm("mov.b64 {%0,%1}, %2;" : "=r"(lo), "=r"(hi) : "l"(v));
    return make_float2(__uint_as_float(lo), __uint_as_float(hi));
}

// ---------------- mma helpers (baseline sm_80+ ISA) ----------------
__device__ __forceinline__ uint32_t smem_u32(const void* p) {
    uint32_t a;
    asm("{ .reg .u64 t; cvta.to.shared.u64 t, %1; cvt.u32.u64 %0, t; }"
        : "=r"(a) : "l"(p));
    return a;
}
__device__ __forceinline__ void ldsm4(uint32_t (&r)[4], uint32_t addr) {
    asm volatile("ldmatrix.sync.aligned.m8n8.x4.shared.b16 {%0,%1,%2,%3}, [%4];"
                 : "=r"(r[0]), "=r"(r[1]), "=r"(r[2]), "=r"(r[3]) : "r"(addr));
}
__device__ __forceinline__ void mma16816(float (&d)[4], const uint32_t (&a)[4],
                                         uint32_t b0, uint32_t b1) {
    asm volatile("mma.sync.aligned.m16n8k16.row.col.f32.bf16.bf16.f32 "
                 "{%0,%1,%2,%3}, {%4,%5,%6,%7}, {%8,%9}, {%0,%1,%2,%3};"
                 : "+f"(d[0]), "+f"(d[1]), "+f"(d[2]), "+f"(d[3])
                 : "r"(a[0]), "r"(a[1]), "r"(a[2]), "r"(a[3]),
                   "r"(b0), "r"(b1));
}
__device__ __forceinline__ void cpasync16(uint32_t dst, const void* src) {
    asm volatile("cp.async.cg.shared.global [%0], [%1], 16;"
                 :: "r"(dst), "l"(src) : "memory");
}
#define CP_COMMIT() asm volatile("cp.async.commit_group;" ::: "memory")
#define CP_WAIT1()  asm volatile("cp.async.wait_group 1;"  ::: "memory")
#define CP_WAIT0()  asm volatile("cp.async.wait_group 0;"  ::: "memory")

// ---------------------------------------------------------------------------
// grid barrier for the co-resident build kernel (volatile poll, no RMW spin)
// ---------------------------------------------------------------------------
__device__ __forceinline__ void gsync(int target)
{
    __threadfence();
    __syncthreads();
    if (threadIdx.x == 0) {
        atomicAdd(&g_gsync, 1);
        volatile int* p = &g_gsync;
        while (*p < target) { }
    }
    __syncthreads();
}

// ---------------------------------------------------------------------------
// Fused CSR build + coeff bf16 hi/lo prep
// ---------------------------------------------------------------------------
__global__ __launch_bounds__(256) void build_csr_kernel(
    const int* __restrict__ erow, const int* __restrict__ ecol,
    const float* __restrict__ ew,
    const float* __restrict__ c1, const float* __restrict__ c2)
{
    __shared__ int sh[256];
    __shared__ int off_sh;
    const int b   = blockIdx.x;
    const int tid = threadIdx.x;
    const int gt  = b * 256 + tid;

    // phase 0a: coeff split -> bf16 hi/lo tiles
    for (int idx = gt; idx < 2 * 64 * 1024; idx += 256 * NB) {
        int L   = idx >> 16;
        int rem = idx & 65535;
        int j   = rem >> 10;
        int f   = rem & 1023;
        const float* cf = L ? c2 : c1;
        int i = f >> 4, br = (f >> 3) & 1, k = f & 7;
        float v = cf[(((size_t)br * HID + j) * HID + i) * GRD + k];
        __nv_bfloat16 vh = __float2bfloat16(v);
        __nv_bfloat16 vl = __float2bfloat16(v - __bfloat162float(vh));
        int t = f >> 6, kk = f & 63;
        g_Ch[L][(t * 64 + j) * 64 + kk] = vh;
        g_Cl[L][(t * 64 + j) * 64 + kk] = vl;
    }

    // phase 0b: histogram over rows (grid-stride)
    for (int e = gt; e < NE; e += 256 * NB)
        atomicAdd(&g_cnt[erow[e]], 1);
    gsync(NB);

    // phase 1: block-local exclusive scan of counts
    int v = (gt < NN) ? __ldcg(&g_cnt[gt]) : 0;
    sh[tid] = v;
    __syncthreads();
    for (int off = 1; off < 256; off <<= 1) {
        int t = (tid >= off) ? sh[tid - off] : 0;
        __syncthreads();
        if (tid >= off) sh[tid] += t;
        __syncthreads();
    }
    int locpre = sh[tid] - v;
    if (tid == 255) g_bsum[b] = sh[255];
    gsync(2 * NB);

    // phase 2: block offsets; init rowstart + cursors
    if (tid == 0) {
        int s = 0;
        for (int j = 0; j < b; j++) s += __ldcg(&g_bsum[j]);
        off_sh = s;
    }
    __syncthreads();
    if (gt < NN) {
        int rs = off_sh + locpre;
        g_rowstart[gt] = rs;
        g_cur[gt]      = rs;
        if (gt == NN - 1) g_rowstart[NN] = rs + v;
    }
    gsync(3 * NB);

    // phase 3: re-arm counters + scatter edges
    if (gt < NN) g_cnt[gt] = 0;
    for (int e = gt; e < NE; e += 256 * NB) {
        int r = erow[e];
        unsigned c = (unsigned)ecol[e];
        unsigned w = __float_as_uint(ew[e]);
        int pos = atomicAdd(&g_cur[r], 1);
        g_edges[pos] = ((ull)w << 32) | (ull)c;
    }
}

// ---------------------------------------------------------------------------
// CSR spmm: warp per destination row, lane = 2 features, unroll-8 gather.
// ---------------------------------------------------------------------------
__global__ __launch_bounds__(256) void spmm_csr_kernel(
    const float* __restrict__ xin, float* __restrict__ xout)
{
    const int node = blockIdx.x * 8 + (threadIdx.x >> 5);
    const int lane = threadIdx.x & 31;
    if (node >= NN) return;

    const int s = g_rowstart[node];
    const int e = g_rowstart[node + 1];
    const ull* __restrict__ xin2 = reinterpret_cast<const ull*>(xin);

    ull acc = 0ULL;
    int i = s;
    for (; i + 8 <= e; i += 8) {
        ull p0 = __ldg(g_edges + i + 0), p1 = __ldg(g_edges + i + 1);
        ull p2 = __ldg(g_edges + i + 2), p3 = __ldg(g_edges + i + 3);
        ull p4 = __ldg(g_edges + i + 4), p5 = __ldg(g_edges + i + 5);
        ull p6 = __ldg(g_edges + i + 6), p7 = __ldg(g_edges + i + 7);
        ull v0 = __ldg(xin2 + (size_t)(unsigned)p0 * 32 + lane);
        ull v1 = __ldg(xin2 + (size_t)(unsigned)p1 * 32 + lane);
        ull v2 = __ldg(xin2 + (size_t)(unsigned)p2 * 32 + lane);
        ull v3 = __ldg(xin2 + (size_t)(unsigned)p3 * 32 + lane);
        ull v4 = __ldg(xin2 + (size_t)(unsigned)p4 * 32 + lane);
        ull v5 = __ldg(xin2 + (size_t)(unsigned)p5 * 32 + lane);
        ull v6 = __ldg(xin2 + (size_t)(unsigned)p6 * 32 + lane);
        ull v7 = __ldg(xin2 + (size_t)(unsigned)p7 * 32 + lane);
        fma2(acc, pk2(__uint_as_float((unsigned)(p0 >> 32))), v0);
        fma2(acc, pk2(__uint_as_float((unsigned)(p1 >> 32))), v1);
        fma2(acc, pk2(__uint_as_float((unsigned)(p2 >> 32))), v2);
        fma2(acc, pk2(__uint_as_float((unsigned)(p3 >> 32))), v3);
        fma2(acc, pk2(__uint_as_float((unsigned)(p4 >> 32))), v4);
        fma2(acc, pk2(__uint_as_float((unsigned)(p5 >> 32))), v5);
        fma2(acc, pk2(__uint_as_float((unsigned)(p6 >> 32))), v6);
        fma2(acc, pk2(__uint_as_float((unsigned)(p7 >> 32))), v7);
    }
    for (; i + 2 <= e; i += 2) {
        ull p0 = __ldg(g_edges + i + 0), p1 = __ldg(g_edges + i + 1);
        ull v0 = __ldg(xin2 + (size_t)(unsigned)p0 * 32 + lane);
        ull v1 = __ldg(xin2 + (size_t)(unsigned)p1 * 32 + lane);
        fma2(acc, pk2(__uint_as_float((unsigned)(p0 >> 32))), v0);
        fma2(acc, pk2(__uint_as_float((unsigned)(p1 >> 32))), v1);
    }
    if (i < e) {
        ull p = __ldg(g_edges + i);
        ull v = __ldg(xin2 + (size_t)(unsigned)p * 32 + lane);
        fma2(acc, pk2(__uint_as_float((unsigned)(p >> 32))), v);
    }
    reinterpret_cast<ull*>(xout)[(size_t)node * 32 + lane] = acc;
}

// ---------------------------------------------------------------------------
// h = x @ W_in + b_in -> bufA.  Also resets the build grid-barrier counter.
// ---------------------------------------------------------------------------
__global__ __launch_bounds__(256) void lin_in_kernel(
    const float* __restrict__ x, const float* __restrict__ W,
    const float* __restrict__ b)
{
    if (blockIdx.x == 0 && threadIdx.x == 0) g_gsync = 0;

    __shared__ float xs[16][INF];
    __shared__ float ws[INF * HID];
    const int n0  = blockIdx.x * 16;
    const int tid = threadIdx.x;

    for (int idx = tid; idx < INF * HID / 4; idx += 256)
        reinterpret_cast<float4*>(ws)[idx] =
            reinterpret_cast<const float4*>(W)[idx];
    for (int idx = tid; idx < 16 * INF; idx += 256) {
        int n = idx >> 7, c = idx & 127;
        xs[n][c] = x[(size_t)(n0 + n) * INF + c];
    }
    __syncthreads();

    const int j4 = (tid & 15) * 4;
    const int ny = tid >> 4;
    const int n  = n0 + ny;

    ull a01 = 0ULL, a23 = 0ULL;
#pragma unroll 8
    for (int i = 0; i < INF; i++) {
        ull xv = pk2(xs[ny][i]);
        const ull* w2 = reinterpret_cast<const ull*>(ws + i * HID + j4);
        fma2(a01, xv, w2[0]);
        fma2(a23, xv, w2[1]);
    }
    float2 v01 = up2(a01), v23 = up2(a23);
    *reinterpret_cast<float4*>(g_bufA + (size_t)n * HID + j4) =
        make_float4(v01.x + b[j4], v01.y + b[j4 + 1],
                    v23.x + b[j4 + 2], v23.y + b[j4 + 3]);
}

// ---------------------------------------------------------------------------
// KAN layer on tensor cores v2.
// SW128-swizzled feature/coeff tiles, cp.async double-buffered coeffs,
// 64 KB smem -> 3 CTAs/SM. Optionally fuses lin_out + log_softmax (layer 2).
// smem map: fh [128 rows x 128B] @0, fl @16384, cbuf[2][hi/lo] @32768 (16384 ea)
// fused epilogue reuse: hsm f32[128][66] @0, wout f32[64][40] @33792
// ---------------------------------------------------------------------------
#define FH_OFF  0
#define FL_OFF  16384
#define CB_OFF  32768
#define KAN_SMEM 65536

template<bool FUSED>
__global__ __launch_bounds__(256, 3) void kan_mma_kernel(
    const float* __restrict__ xin,
    const __nv_bfloat16* __restrict__ Ch,
    const __nv_bfloat16* __restrict__ Cl,
    float* __restrict__ xout,
    const float* __restrict__ Wout,
    float* __restrict__ outp)
{
    extern __shared__ char sm[];
    const int tid   = threadIdx.x;
    const int lane  = tid & 31;
    const int wid   = tid >> 5;
    const int warpM = wid & 3;
    const int warpN = wid >> 2;
    const int n0    = blockIdx.x * 128;
    const uint32_t sbase = smem_u32(sm);
    const int sel  = lane >> 3;
    const int lrow = lane & 7;

    const char* ChB = reinterpret_cast<const char*>(Ch);
    const char* ClB = reinterpret_cast<const char*>(Cl);

    // issue copy of coeff tile 0 into buffer 0
    {
#pragma unroll
        for (int r = 0; r < 4; r++) {
            int idx = tid + 256 * r;
            int mat = idx >> 9, rem = idx & 511;
            int j = rem >> 3, c = rem & 7;
            uint32_t dst = sbase + CB_OFF + mat * 8192
                         + j * 128 + ((c ^ (j & 7)) * 16);
            const char* src = (mat ? ClB : ChB) + (size_t)j * 128 + c * 16;
            cpasync16(dst, src);
        }
        CP_COMMIT();
    }

    float acc[2][4][4];
#pragma unroll
    for (int m = 0; m < 2; m++)
#pragma unroll
        for (int nt = 0; nt < 4; nt++)
#pragma unroll
            for (int q = 0; q < 4; q++) acc[m][nt][q] = 0.f;

    const int fn  = tid & 127;         // featgen node (local)
    const int fi0 = tid >> 7;          // featgen ii for r=0 (0 or 1)

    for (int t = 0; t < 16; t++) {
        const int buf = t & 1;
        __syncthreads();               // mma(t-1) done: fh/fl & cbuf[buf^1] free

        if (t + 1 < 16) {              // prefetch coeff tile t+1
#pragma unroll
            for (int r = 0; r < 4; r++) {
                int idx = tid + 256 * r;
                int mat = idx >> 9, rem = idx & 511;
                int j = rem >> 3, c = rem & 7;
                uint32_t dst = sbase + CB_OFF + (buf ^ 1) * 16384 + mat * 8192
                             + j * 128 + ((c ^ (j & 7)) * 16);
                const char* src = (mat ? ClB : ChB)
                                + ((size_t)(t + 1) * 64 + j) * 128 + c * 16;
                cpasync16(dst, src);
            }
            CP_COMMIT();
        }

        // ---- featgen: this thread covers (fn, fi0) and (fn, fi0+2) ----
        {
            float xva = __ldg(xin + (size_t)(n0 + fn) * HID + t * 4 + fi0);
            float xvb = __ldg(xin + (size_t)(n0 + fn) * HID + t * 4 + fi0 + 2);
#pragma unroll
            for (int r = 0; r < 2; r++) {
                int   ii = fi0 + 2 * r;
                float xv = r ? xvb : xva;
                float s1, c1;
                __sincosf(xv, &s1, &c1);
                float cc[8], ss[8];
                cc[0] = c1; ss[0] = s1;
                float tw = 2.f * c1;
                float cm2 = 1.f, cm1 = c1, sm2 = 0.f, sm1 = s1;
#pragma unroll
                for (int k = 1; k < 8; k++) {
                    float cn = tw * cm1 - cm2;
                    float sn = tw * sm1 - sm2;
                    cc[k] = cn; ss[k] = sn;
                    cm2 = cm1; cm1 = cn; sm2 = sm1; sm1 = sn;
                }
                uint32_t chh[4], chl[4], shh[4], shl[4];
#pragma unroll
                for (int m = 0; m < 4; m++) {
                    __nv_bfloat162 h2 = __floats2bfloat162_rn(cc[2*m], cc[2*m+1]);
                    __nv_bfloat162 l2 = __floats2bfloat162_rn(
                        cc[2*m]   - __bfloat162float(h2.x),
                        cc[2*m+1] - __bfloat162float(h2.y));
                    chh[m] = *reinterpret_cast<uint32_t*>(&h2);
                    chl[m] = *reinterpret_cast<uint32_t*>(&l2);
                    h2 = __floats2bfloat162_rn(ss[2*m], ss[2*m+1]);
                    l2 = __floats2bfloat162_rn(
                        ss[2*m]   - __bfloat162float(h2.x),
                        ss[2*m+1] - __bfloat162float(h2.y));
                    shh[m] = *reinterpret_cast<uint32_t*>(&h2);
                    shl[m] = *reinterpret_cast<uint32_t*>(&l2);
                }
                uint32_t rowoff = (uint32_t)fn * 128;
                uint32_t cchunk = (uint32_t)((2 * ii)     ^ (fn & 7)) * 16;
                uint32_t schunk = (uint32_t)((2 * ii + 1) ^ (fn & 7)) * 16;
                *reinterpret_cast<uint4*>(sm + FH_OFF + rowoff + cchunk) =
                    make_uint4(chh[0], chh[1], chh[2], chh[3]);
                *reinterpret_cast<uint4*>(sm + FH_OFF + rowoff + schunk) =
                    make_uint4(shh[0], shh[1], shh[2], shh[3]);
                *reinterpret_cast<uint4*>(sm + FL_OFF + rowoff + cchunk) =
                    make_uint4(chl[0], chl[1], chl[2], chl[3]);
                *reinterpret_cast<uint4*>(sm + FL_OFF + rowoff + schunk) =
                    make_uint4(shl[0], shl[1], shl[2], shl[3]);
            }
        }

        if (t + 1 < 16) CP_WAIT1(); else CP_WAIT0();
        __syncthreads();               // fh/fl + cbuf[buf] ready for all

        // ---- mma over 4 k-steps ----
#pragma unroll
        for (int ks = 0; ks < 4; ks++) {
            uint32_t ah[2][4], al[2][4];
#pragma unroll
            for (int m = 0; m < 2; m++) {
                uint32_t rowA = (uint32_t)(warpM * 32 + m * 16 + lrow + (sel & 1) * 8);
                uint32_t ca   = (uint32_t)((2 * ks + (sel >> 1)) ^ lrow) * 16;
                uint32_t ra   = sbase + FH_OFF + rowA * 128 + ca;
                ldsm4(ah[m], ra);
                ldsm4(al[m], ra + (FL_OFF - FH_OFF));
            }
            const uint32_t cbb = sbase + CB_OFF + (uint32_t)buf * 16384;
#pragma unroll
            for (int pi = 0; pi < 2; pi++) {
                uint32_t rowB = (uint32_t)(warpN * 32 + pi * 16 + lrow + (sel >> 1) * 8);
                uint32_t cb   = (uint32_t)((2 * ks + (sel & 1)) ^ lrow) * 16;
                uint32_t rb   = cbb + rowB * 128 + cb;
                uint32_t bh[4], bl[4];
                ldsm4(bh, rb);
                ldsm4(bl, rb + 8192);
#pragma unroll
                for (int ntl = 0; ntl < 2; ntl++) {
                    uint32_t b0h = bh[ntl * 2], b1h = bh[ntl * 2 + 1];
                    uint32_t b0l = bl[ntl * 2], b1l = bl[ntl * 2 + 1];
                    int nt = pi * 2 + ntl;
#pragma unroll
                    for (int m = 0; m < 2; m++) {
                        mma16816(acc[m][nt], ah[m], b0h, b1h);
                        mma16816(acc[m][nt], al[m], b0h, b1h);
                        mma16816(acc[m][nt], ah[m], b0l, b1l);
                    }
                }
            }
        }
    }

    const int g2 = lane >> 2, c4 = lane & 3;

    if (!FUSED) {
        // write acc fragments straight to global
#pragma unroll
        for (int m = 0; m < 2; m++) {
#pragma unroll
            for (int nt = 0; nt < 4; nt++) {
                int row0 = n0 + warpM * 32 + m * 16 + g2;
                int col  = warpN * 32 + nt * 8 + c4 * 2;
                *reinterpret_cast<float2*>(xout + (size_t)row0 * HID + col) =
                    make_float2(acc[m][nt][0], acc[m][nt][1]);
                *reinterpret_cast<float2*>(xout + (size_t)(row0 + 8) * HID + col) =
                    make_float2(acc[m][nt][2], acc[m][nt][3]);
            }
        }
    } else {
        // fused lin_out + log_softmax epilogue
        __syncthreads();               // all mma reads of smem done
        float* hsm = reinterpret_cast<float*>(sm);          // [128][66]
        float* wsm = reinterpret_cast<float*>(sm + 33792);  // [64][40]
        for (int q = tid; q < HID * OUTF; q += 256) wsm[q] = Wout[q];
#pragma unroll
        for (int m = 0; m < 2; m++) {
#pragma unroll
            for (int nt = 0; nt < 4; nt++) {
                int row = warpM * 32 + m * 16 + g2;
                int col = warpN * 32 + nt * 8 + c4 * 2;
                *reinterpret_cast<float2*>(hsm + row * 66 + col) =
                    make_float2(acc[m][nt][0], acc[m][nt][1]);
                *reinterpret_cast<float2*>(hsm + (row + 8) * 66 + col) =
                    make_float2(acc[m][nt][2], acc[m][nt][3]);
            }
        }
        __syncthreads();

        const int node = tid >> 1;
        const int half = tid & 1;
        float v[20];
#pragma unroll
        for (int q = 0; q < 20; q++) v[q] = 0.f;
#pragma unroll 8
        for (int i = 0; i < HID; i++) {
            float h = hsm[node * 66 + i];
            const float4* wr = reinterpret_cast<const float4*>(
                wsm + i * OUTF + half * 20);
#pragma unroll
            for (int q = 0; q < 5; q++) {
                float4 w = wr[q];
                v[4*q+0] += h * w.x; v[4*q+1] += h * w.y;
                v[4*q+2] += h * w.z; v[4*q+3] += h * w.w;
            }
        }
        float mx = v[0];
#pragma unroll
        for (int q = 1; q < 20; q++) mx = fmaxf(mx, v[q]);
        mx = fmaxf(mx, __shfl_xor_sync(0xFFFFFFFFu, mx, 1));
        float e = 0.f;
#pragma unroll
        for (int q = 0; q < 20; q++) e += __expf(v[q] - mx);
        e += __shfl_xor_sync(0xFFFFFFFFu, e, 1);
        float ls = mx + __logf(e);
        int gn = n0 + node;
        if (gn < NN) {
            float* dst = outp + (size_t)gn * OUTF + half * 20;
#pragma unroll
            for (int q = 0; q < 20; q++) dst[q] = v[q] - ls;
        }
    }
}

// ---------------------------------------------------------------------------
extern "C" void kernel_launch(void* const* d_in, const int* in_sizes, int n_in,
                              void* d_out, int out_size)
{
    const float* x     = (const float*)d_in[0];
    const int*   erow  = (const int*)  d_in[1];
    const int*   ecol  = (const int*)  d_in[2];
    const float* ew    = (const float*)d_in[3];
    const float* W_in  = (const float*)d_in[4];
    const float* b_in  = (const float*)d_in[5];
    const float* c1    = (const float*)d_in[6];
    const float* c2    = (const float*)d_in[7];
    const float* W_out = (const float*)d_in[8];
    float* out = (float*)d_out;

    float *bufA = nullptr, *bufB = nullptr;
    __nv_bfloat16 *chp = nullptr, *clp = nullptr;
    cudaGetSymbolAddress((void**)&bufA, g_bufA);
    cudaGetSymbolAddress((void**)&bufB, g_bufB);
    cudaGetSymbolAddress((void**)&chp,  g_Ch);
    cudaGetSymbolAddress((void**)&clp,  g_Cl);

    cudaFuncSetAttribute(kan_mma_kernel<false>,
                         cudaFuncAttributeMaxDynamicSharedMemorySize, KAN_SMEM);
    cudaFuncSetAttribute(kan_mma_kernel<true>,
                         cudaFuncAttributeMaxDynamicSharedMemorySize, KAN_SMEM);

    const int kanBlocks  = NNP / 128;          // 782
    const int spmmBlocks = (NN + 7) / 8;
    const size_t cl_sz   = (size_t)16 * 64 * 64;   // bf16 per layer

    build_csr_kernel<<<NB, 256>>>(erow, ecol, ew, c1, c2);              // 0
    lin_in_kernel<<<NN / 16, 256>>>(x, W_in, b_in);                     // 1
    spmm_csr_kernel<<<spmmBlocks, 256>>>(bufA, bufB);                   // 2
    kan_mma_kernel<false><<<kanBlocks, 256, KAN_SMEM>>>(
        bufB, chp, clp, bufA, nullptr, nullptr);                        // 3
    spmm_csr_kernel<<<spmmBlocks, 256>>>(bufA, bufB);                   // 4
    kan_mma_kernel<true><<<kanBlocks, 256, KAN_SMEM>>>(
        bufB, chp + cl_sz, clp + cl_sz, nullptr, W_out, out);           // 5 <- profiled
}

// round 11
// speedup vs baseline: 2.2872x; 1.0479x over previous
#include <cuda_runtime.h>
#include <cuda_bf16.h>
#include <cuda_fp16.h>
#include <math.h>
#include <stdint.h>

#define NN    100000
#define NNP   100096          // padded to multiple of 128
#define NE    1600000
#define INF   128
#define HID   64
#define OUTF  40
#define GRD   8
#define NB    391             // build grid: ceil(NN/256), all co-resident

typedef unsigned long long ull;

// ------------------------- scratch (no cudaMalloc) -------------------------
__device__ float g_bufA[(size_t)NNP * HID];
__device__ float g_bufB[(size_t)NNP * HID];
__device__ int   g_rowstart[NN + 1];
__device__ int   g_cnt[NN];            // zeroed in build phase 3 each replay
__device__ int   g_cur[NN];
__device__ int   g_bsum[NB];
__device__ ull   g_edges[NE];          // packed (w<<32 | col), CSR by row
__device__ int   g_gsync;              // grid barrier counter; reset by lin_in
// 16-bit split coeffs: layer 0 = bf16 hi/lo, layer 1 = fp16 hi/lo
// layout: [layer][tile 0..15][j 0..63][kk 0..63]
__device__ unsigned short g_Ch[2][16 * 64 * 64];
__device__ unsigned short g_Cl[2][16 * 64 * 64];

// ---------------- f32x2 helpers (spmm / lin_in) ----------------
__device__ __forceinline__ ull pk2(float s) {
    ull d; unsigned u = __float_as_uint(s);
    asm("mov.b64 %0, {%1,%1};" : "=l"(d) : "r"(u));
    return d;
}
__device__ __forceinline__ void fma2(ull& d, ull a, ull b) {
    asm("fma.rn.f32x2 %0, %1, %2, %0;" : "+l"(d) : "l"(a), "l"(b));
}
__device__ __forceinline__ float2 up2(ull v) {
    unsigned lo, hi;
    asm("mov.b64 {%0,%1}, %2;" : "=r"(lo), "=r"(hi) : "l"(v));
    return make_float2(__uint_as_float(lo), __uint_as_float(hi));
}

// ---------------- mma helpers (baseline sm_80+ ISA) ----------------
__device__ __forceinline__ uint32_t smem_u32(const void* p) {
    uint32_t a;
    asm("{ .reg .u64 t; cvta.to.shared.u64 t, %1; cvt.u32.u64 %0, t; }"
        : "=r"(a) : "l"(p));
    return a;
}
__device__ __forceinline__ void ldsm4(uint32_t (&r)[4], uint32_t addr) {
    asm volatile("ldmatrix.sync.aligned.m8n8.x4.shared.b16 {%0,%1,%2,%3}, [%4];"
                 : "=r"(r[0]), "=r"(r[1]), "=r"(r[2]), "=r"(r[3]) : "r"(addr));
}
__device__ __forceinline__ void mma_bf16(float (&d)[4], const uint32_t (&a)[4],
                                         uint32_t b0, uint32_t b1) {
    asm volatile("mma.sync.aligned.m16n8k16.row.col.f32.bf16.bf16.f32 "
                 "{%0,%1,%2,%3}, {%4,%5,%6,%7}, {%8,%9}, {%0,%1,%2,%3};"
                 : "+f"(d[0]), "+f"(d[1]), "+f"(d[2]), "+f"(d[3])
                 : "r"(a[0]), "r"(a[1]), "r"(a[2]), "r"(a[3]),
                   "r"(b0), "r"(b1));
}
__device__ __forceinline__ void mma_f16(float (&d)[4], const uint32_t (&a)[4],
                                        uint32_t b0, uint32_t b1) {
    asm volatile("mma.sync.aligned.m16n8k16.row.col.f32.f16.f16.f32 "
                 "{%0,%1,%2,%3}, {%4,%5,%6,%7}, {%8,%9}, {%0,%1,%2,%3};"
                 : "+f"(d[0]), "+f"(d[1]), "+f"(d[2]), "+f"(d[3])
                 : "r"(a[0]), "r"(a[1]), "r"(a[2]), "r"(a[3]),
                   "r"(b0), "r"(b1));
}
__device__ __forceinline__ void cpasync16(uint32_t dst, const void* src) {
    asm volatile("cp.async.cg.shared.global [%0], [%1], 16;"
                 :: "r"(dst), "l"(src) : "memory");
}
#define CP_COMMIT() asm volatile("cp.async.commit_group;" ::: "memory")
#define CP_WAIT1()  asm volatile("cp.async.wait_group 1;"  ::: "memory")
#define CP_WAIT0()  asm volatile("cp.async.wait_group 0;"  ::: "memory")

// ---------------------------------------------------------------------------
// grid barrier for the co-resident build kernel
// ---------------------------------------------------------------------------
__device__ __forceinline__ void gsync(int target)
{
    __threadfence();
    __syncthreads();
    if (threadIdx.x == 0) {
        atomicAdd(&g_gsync, 1);
        volatile int* p = &g_gsync;
        while (*p < target) { }
    }
    __syncthreads();
}

// ---------------------------------------------------------------------------
// Fused CSR build + coeff split prep (layer0: bf16 hi/lo; layer1: fp16 hi/lo)
// ---------------------------------------------------------------------------
__global__ __launch_bounds__(256) void build_csr_kernel(
    const int* __restrict__ erow, const int* __restrict__ ecol,
    const float* __restrict__ ew,
    const float* __restrict__ c1, const float* __restrict__ c2)
{
    __shared__ int sh[256];
    __shared__ int off_sh;
    const int b   = blockIdx.x;
    const int tid = threadIdx.x;
    const int gt  = b * 256 + tid;

    // phase 0a: coeff split
    for (int idx = gt; idx < 2 * 64 * 1024; idx += 256 * NB) {
        int L   = idx >> 16;
        int rem = idx & 65535;
        int j   = rem >> 10;
        int f   = rem & 1023;
        const float* cf = L ? c2 : c1;
        int i = f >> 4, br = (f >> 3) & 1, k = f & 7;
        float v = cf[(((size_t)br * HID + j) * HID + i) * GRD + k];
        unsigned short hb, lb;
        if (L == 0) {
            __nv_bfloat16 vh = __float2bfloat16(v);
            __nv_bfloat16 vl = __float2bfloat16(v - __bfloat162float(vh));
            hb = *reinterpret_cast<unsigned short*>(&vh);
            lb = *reinterpret_cast<unsigned short*>(&vl);
        } else {
            __half vh = __float2half_rn(v);
            __half vl = __float2half_rn(v - __half2float(vh));
            hb = *reinterpret_cast<unsigned short*>(&vh);
            lb = *reinterpret_cast<unsigned short*>(&vl);
        }
        int t = f >> 6, kk = f & 63;
        g_Ch[L][(t * 64 + j) * 64 + kk] = hb;
        g_Cl[L][(t * 64 + j) * 64 + kk] = lb;
    }

    // phase 0b: histogram over rows
    for (int e = gt; e < NE; e += 256 * NB)
        atomicAdd(&g_cnt[erow[e]], 1);
    gsync(NB);

    // phase 1: block-local exclusive scan
    int v = (gt < NN) ? __ldcg(&g_cnt[gt]) : 0;
    sh[tid] = v;
    __syncthreads();
    for (int off = 1; off < 256; off <<= 1) {
        int t = (tid >= off) ? sh[tid - off] : 0;
        __syncthreads();
        if (tid >= off) sh[tid] += t;
        __syncthreads();
    }
    int locpre = sh[tid] - v;
    if (tid == 255) g_bsum[b] = sh[255];
    gsync(2 * NB);

    // phase 2: block offsets; init rowstart + cursors
    if (tid == 0) {
        int s = 0;
        for (int j = 0; j < b; j++) s += __ldcg(&g_bsum[j]);
        off_sh = s;
    }
    __syncthreads();
    if (gt < NN) {
        int rs = off_sh + locpre;
        g_rowstart[gt] = rs;
        g_cur[gt]      = rs;
        if (gt == NN - 1) g_rowstart[NN] = rs + v;
    }
    gsync(3 * NB);

    // phase 3: re-arm counters + scatter edges
    if (gt < NN) g_cnt[gt] = 0;
    for (int e = gt; e < NE; e += 256 * NB) {
        int r = erow[e];
        unsigned c = (unsigned)ecol[e];
        unsigned w = __float_as_uint(ew[e]);
        int pos = atomicAdd(&g_cur[r], 1);
        g_edges[pos] = ((ull)w << 32) | (ull)c;
    }
}

// ---------------------------------------------------------------------------
// CSR spmm: warp per destination row, lane = 2 features, unroll-8 gather.
// ---------------------------------------------------------------------------
__global__ __launch_bounds__(256) void spmm_csr_kernel(
    const float* __restrict__ xin, float* __restrict__ xout)
{
    const int node = blockIdx.x * 8 + (threadIdx.x >> 5);
    const int lane = threadIdx.x & 31;
    if (node >= NN) return;

    const int s = g_rowstart[node];
    const int e = g_rowstart[node + 1];
    const ull* __restrict__ xin2 = reinterpret_cast<const ull*>(xin);

    ull acc = 0ULL;
    int i = s;
    for (; i + 8 <= e; i += 8) {
        ull p0 = __ldg(g_edges + i + 0), p1 = __ldg(g_edges + i + 1);
        ull p2 = __ldg(g_edges + i + 2), p3 = __ldg(g_edges + i + 3);
        ull p4 = __ldg(g_edges + i + 4), p5 = __ldg(g_edges + i + 5);
        ull p6 = __ldg(g_edges + i + 6), p7 = __ldg(g_edges + i + 7);
        ull v0 = __ldg(xin2 + (size_t)(unsigned)p0 * 32 + lane);
        ull v1 = __ldg(xin2 + (size_t)(unsigned)p1 * 32 + lane);
        ull v2 = __ldg(xin2 + (size_t)(unsigned)p2 * 32 + lane);
        ull v3 = __ldg(xin2 + (size_t)(unsigned)p3 * 32 + lane);
        ull v4 = __ldg(xin2 + (size_t)(unsigned)p4 * 32 + lane);
        ull v5 = __ldg(xin2 + (size_t)(unsigned)p5 * 32 + lane);
        ull v6 = __ldg(xin2 + (size_t)(unsigned)p6 * 32 + lane);
        ull v7 = __ldg(xin2 + (size_t)(unsigned)p7 * 32 + lane);
        fma2(acc, pk2(__uint_as_float((unsigned)(p0 >> 32))), v0);
        fma2(acc, pk2(__uint_as_float((unsigned)(p1 >> 32))), v1);
        fma2(acc, pk2(__uint_as_float((unsigned)(p2 >> 32))), v2);
        fma2(acc, pk2(__uint_as_float((unsigned)(p3 >> 32))), v3);
        fma2(acc, pk2(__uint_as_float((unsigned)(p4 >> 32))), v4);
        fma2(acc, pk2(__uint_as_float((unsigned)(p5 >> 32))), v5);
        fma2(acc, pk2(__uint_as_float((unsigned)(p6 >> 32))), v6);
        fma2(acc, pk2(__uint_as_float((unsigned)(p7 >> 32))), v7);
    }
    for (; i + 2 <= e; i += 2) {
        ull p0 = __ldg(g_edges + i + 0), p1 = __ldg(g_edges + i + 1);
        ull v0 = __ldg(xin2 + (size_t)(unsigned)p0 * 32 + lane);
        ull v1 = __ldg(xin2 + (size_t)(unsigned)p1 * 32 + lane);
        fma2(acc, pk2(__uint_as_float((unsigned)(p0 >> 32))), v0);
        fma2(acc, pk2(__uint_as_float((unsigned)(p1 >> 32))), v1);
    }
    if (i < e) {
        ull p = __ldg(g_edges + i);
        ull v = __ldg(xin2 + (size_t)(unsigned)p * 32 + lane);
        fma2(acc, pk2(__uint_as_float((unsigned)(p >> 32))), v);
    }
    reinterpret_cast<ull*>(xout)[(size_t)node * 32 + lane] = acc;
}

// ---------------------------------------------------------------------------
// h = x @ W_in + b_in -> bufA.  Also resets the build grid-barrier counter.
// ---------------------------------------------------------------------------
__global__ __launch_bounds__(256) void lin_in_kernel(
    const float* __restrict__ x, const float* __restrict__ W,
    const float* __restrict__ b)
{
    if (blockIdx.x == 0 && threadIdx.x == 0) g_gsync = 0;

    __shared__ float xs[16][INF];
    __shared__ float ws[INF * HID];
    const int n0  = blockIdx.x * 16;
    const int tid = threadIdx.x;

    for (int idx = tid; idx < INF * HID / 4; idx += 256)
        reinterpret_cast<float4*>(ws)[idx] =
            reinterpret_cast<const float4*>(W)[idx];
    for (int idx = tid; idx < 16 * INF; idx += 256) {
        int n = idx >> 7, c = idx & 127;
        xs[n][c] = x[(size_t)(n0 + n) * INF + c];
    }
    __syncthreads();

    const int j4 = (tid & 15) * 4;
    const int ny = tid >> 4;
    const int n  = n0 + ny;

    ull a01 = 0ULL, a23 = 0ULL;
#pragma unroll 8
    for (int i = 0; i < INF; i++) {
        ull xv = pk2(xs[ny][i]);
        const ull* w2 = reinterpret_cast<const ull*>(ws + i * HID + j4);
        fma2(a01, xv, w2[0]);
        fma2(a23, xv, w2[1]);
    }
    float2 v01 = up2(a01), v23 = up2(a23);
    *reinterpret_cast<float4*>(g_bufA + (size_t)n * HID + j4) =
        make_float4(v01.x + b[j4], v01.y + b[j4 + 1],
                    v23.x + b[j4 + 2], v23.y + b[j4 + 3]);
}

// ---------------------------------------------------------------------------
// KAN layer v3: pipelined featgen/mma overlap, single sync per tile.
// !FUSED (layer 1): bf16 3-pass, features hi/lo (double-buffered, 96 KB).
//  FUSED (layer 2): fp16 2-pass, features single (double-buffered, 64 KB)
//                   + fused lin_out + log_softmax epilogue.
// smem: fbuf[2] of FB bytes (hi @0, lo @16384 if 3-pass);
//       cbuf[2] of 16 KB (ch @0, cl @8192) at offset 2*FB.
// ---------------------------------------------------------------------------
template<bool FUSED>
__global__ __launch_bounds__(256, 2) void kan_mma_kernel(
    const float* __restrict__ xin,
    const unsigned short* __restrict__ Ch,
    const unsigned short* __restrict__ Cl,
    float* __restrict__ xout,
    const float* __restrict__ Wout,
    float* __restrict__ outp)
{
    constexpr int FB     = FUSED ? 16384 : 32768;
    constexpr int CB_OFF = 2 * FB;

    extern __shared__ char sm[];
    const int tid   = threadIdx.x;
    const int lane  = tid & 31;
    const int wid   = tid >> 5;
    const int warpM = wid & 3;
    const int warpN = wid >> 2;
    const int n0    = blockIdx.x * 128;
    const uint32_t sbase = smem_u32(sm);
    const int sel  = lane >> 3;
    const int lrow = lane & 7;

    const char* ChB = reinterpret_cast<const char*>(Ch);
    const char* ClB = reinterpret_cast<const char*>(Cl);

    const int fn  = tid & 127;         // featgen node (local)
    const int fi0 = tid >> 7;          // featgen base ii (0 or 1)

    // ---- featgen for tile tt into fbuf[bsel] ----
    auto featgen = [&](int tt, int bsel) {
        char* fb = sm + bsel * FB;
#pragma unroll
        for (int r = 0; r < 2; r++) {
            int   ii = fi0 + 2 * r;
            float xv = __ldg(xin + (size_t)(n0 + fn) * HID + tt * 4 + ii);
            float s1, c1;
            __sincosf(xv, &s1, &c1);
            float cc[8], ss[8];
            cc[0] = c1; ss[0] = s1;
            float tw = 2.f * c1;
            float cm2 = 1.f, cm1 = c1, sm2 = 0.f, sm1 = s1;
#pragma unroll
            for (int k = 1; k < 8; k++) {
                float cn = tw * cm1 - cm2;
                float sn = tw * sm1 - sm2;
                cc[k] = cn; ss[k] = sn;
                cm2 = cm1; cm1 = cn; sm2 = sm1; sm1 = sn;
            }
            uint32_t rowoff = (uint32_t)fn * 128;
            uint32_t cchunk = (uint32_t)((2 * ii)     ^ (fn & 7)) * 16;
            uint32_t schunk = (uint32_t)((2 * ii + 1) ^ (fn & 7)) * 16;
            if (FUSED) {
                uint32_t ph[4], psn[4];
#pragma unroll
                for (int m = 0; m < 4; m++) {
                    __half2 h2 = __floats2half2_rn(cc[2*m], cc[2*m+1]);
                    ph[m] = *reinterpret_cast<uint32_t*>(&h2);
                    h2 = __floats2half2_rn(ss[2*m], ss[2*m+1]);
                    psn[m] = *reinterpret_cast<uint32_t*>(&h2);
                }
                *reinterpret_cast<uint4*>(fb + rowoff + cchunk) =
                    make_uint4(ph[0], ph[1], ph[2], ph[3]);
                *reinterpret_cast<uint4*>(fb + rowoff + schunk) =
                    make_uint4(psn[0], psn[1], psn[2], psn[3]);
            } else {
                uint32_t chh[4], chl[4], shh[4], shl[4];
#pragma unroll
                for (int m = 0; m < 4; m++) {
                    __nv_bfloat162 h2 = __floats2bfloat162_rn(cc[2*m], cc[2*m+1]);
                    __nv_bfloat162 l2 = __floats2bfloat162_rn(
                        cc[2*m]   - __bfloat162float(h2.x),
                        cc[2*m+1] - __bfloat162float(h2.y));
                    chh[m] = *reinterpret_cast<uint32_t*>(&h2);
                    chl[m] = *reinterpret_cast<uint32_t*>(&l2);
                    h2 = __floats2bfloat162_rn(ss[2*m], ss[2*m+1]);
                    l2 = __floats2bfloat162_rn(
                        ss[2*m]   - __bfloat162float(h2.x),
                        ss[2*m+1] - __bfloat162float(h2.y));
                    shh[m] = *reinterpret_cast<uint32_t*>(&h2);
                    shl[m] = *reinterpret_cast<uint32_t*>(&l2);
                }
                *reinterpret_cast<uint4*>(fb + rowoff + cchunk) =
                    make_uint4(chh[0], chh[1], chh[2], chh[3]);
                *reinterpret_cast<uint4*>(fb + rowoff + schunk) =
                    make_uint4(shh[0], shh[1], shh[2], shh[3]);
                *reinterpret_cast<uint4*>(fb + 16384 + rowoff + cchunk) =
                    make_uint4(chl[0], chl[1], chl[2], chl[3]);
                *reinterpret_cast<uint4*>(fb + 16384 + rowoff + schunk) =
                    make_uint4(shl[0], shl[1], shl[2], shl[3]);
            }
        }
    };

    // ---- cp.async coeff tile tt into cbuf[bsel] ----
    auto coeff_cp = [&](int tt, int bsel) {
#pragma unroll
        for (int r = 0; r < 4; r++) {
            int idx = tid + 256 * r;
            int mat = idx >> 9, rem = idx & 511;
            int j = rem >> 3, c = rem & 7;
            uint32_t dst = sbase + CB_OFF + bsel * 16384 + mat * 8192
                         + j * 128 + ((c ^ (j & 7)) * 16);
            const char* src = (mat ? ClB : ChB)
                            + ((size_t)tt * 64 + j) * 128 + c * 16;
            cpasync16(dst, src);
        }
        CP_COMMIT();
    };

    // preloop: tile 0 staged
    coeff_cp(0, 0);
    featgen(0, 0);

    float acc[2][4][4];
#pragma unroll
    for (int m = 0; m < 2; m++)
#pragma unroll
        for (int nt = 0; nt < 4; nt++)
#pragma unroll
            for (int q = 0; q < 4; q++) acc[m][nt][q] = 0.f;

    for (int t = 0; t < 16; t++) {
        const int buf = t & 1;
        __syncthreads();               // all warps done with iter t-1 (mma t-1)

        if (t + 1 < 16) {
            coeff_cp(t + 1, buf ^ 1);
            featgen(t + 1, buf ^ 1);
            CP_WAIT1();
        } else {
            CP_WAIT0();
        }

        // ---- mma(t) from fbuf[buf], cbuf[buf] ----
        const uint32_t fbb = sbase + (uint32_t)buf * FB;
        const uint32_t cbb = sbase + CB_OFF + (uint32_t)buf * 16384;
#pragma unroll
        for (int ks = 0; ks < 4; ks++) {
            uint32_t ah[2][4], al[2][4];
#pragma unroll
            for (int m = 0; m < 2; m++) {
                uint32_t rowA = (uint32_t)(warpM * 32 + m * 16 + lrow + (sel & 1) * 8);
                uint32_t ca   = (uint32_t)((2 * ks + (sel >> 1)) ^ lrow) * 16;
                uint32_t ra   = fbb + rowA * 128 + ca;
                ldsm4(ah[m], ra);
                if (!FUSED) ldsm4(al[m], ra + 16384);
            }
#pragma unroll
            for (int pi = 0; pi < 2; pi++) {
                uint32_t rowB = (uint32_t)(warpN * 32 + pi * 16 + lrow + (sel >> 1) * 8);
                uint32_t cb   = (uint32_t)((2 * ks + (sel & 1)) ^ lrow) * 16;
                uint32_t rb   = cbb + rowB * 128 + cb;
                uint32_t bh[4], bl[4];
                ldsm4(bh, rb);
                ldsm4(bl, rb + 8192);
#pragma unroll
                for (int ntl = 0; ntl < 2; ntl++) {
                    uint32_t b0h = bh[ntl * 2], b1h = bh[ntl * 2 + 1];
                    uint32_t b0l = bl[ntl * 2], b1l = bl[ntl * 2 + 1];
                    int nt = pi * 2 + ntl;
#pragma unroll
                    for (int m = 0; m < 2; m++) {
                        if (FUSED) {
                            mma_f16(acc[m][nt], ah[m], b0h, b1h);
                            mma_f16(acc[m][nt], ah[m], b0l, b1l);
                        } else {
                            mma_bf16(acc[m][nt], ah[m], b0h, b1h);
                            mma_bf16(acc[m][nt], al[m], b0h, b1h);
                            mma_bf16(acc[m][nt], ah[m], b0l, b1l);
                        }
                    }
                }
            }
        }
    }

    const int g2 = lane >> 2, c4 = lane & 3;

    if (!FUSED) {
#pragma unroll
        for (int m = 0; m < 2; m++) {
#pragma unroll
            for (int nt = 0; nt < 4; nt++) {
                int row0 = n0 + warpM * 32 + m * 16 + g2;
                int col  = warpN * 32 + nt * 8 + c4 * 2;
                *reinterpret_cast<float2*>(xout + (size_t)row0 * HID + col) =
                    make_float2(acc[m][nt][0], acc[m][nt][1]);
                *reinterpret_cast<float2*>(xout + (size_t)(row0 + 8) * HID + col) =
                    make_float2(acc[m][nt][2], acc[m][nt][3]);
            }
        }
    } else {
        // fused lin_out + log_softmax epilogue
        __syncthreads();               // all mma reads of smem done
        float* hsm = reinterpret_cast<float*>(sm);          // [128][66]
        float* wsm = reinterpret_cast<float*>(sm + 33792);  // [64][40]
        for (int q = tid; q < HID * OUTF; q += 256) wsm[q] = Wout[q];
#pragma unroll
        for (int m = 0; m < 2; m++) {
#pragma unroll
            for (int nt = 0; nt < 4; nt++) {
                int row = warpM * 32 + m * 16 + g2;
                int col = warpN * 32 + nt * 8 + c4 * 2;
                *reinterpret_cast<float2*>(hsm + row * 66 + col) =
                    make_float2(acc[m][nt][0], acc[m][nt][1]);
                *reinterpret_cast<float2*>(hsm + (row + 8) * 66 + col) =
                    make_float2(acc[m][nt][2], acc[m][nt][3]);
            }
        }
        __syncthreads();

        const int node = tid >> 1;
        const int half = tid & 1;
        float v[20];
#pragma unroll
        for (int q = 0; q < 20; q++) v[q] = 0.f;
#pragma unroll 8
        for (int i = 0; i < HID; i++) {
            float h = hsm[node * 66 + i];
            const float4* wr = reinterpret_cast<const float4*>(
                wsm + i * OUTF + half * 20);
#pragma unroll
            for (int q = 0; q < 5; q++) {
                float4 w = wr[q];
                v[4*q+0] += h * w.x; v[4*q+1] += h * w.y;
                v[4*q+2] += h * w.z; v[4*q+3] += h * w.w;
            }
        }
        float mx = v[0];
#pragma unroll
        for (int q = 1; q < 20; q++) mx = fmaxf(mx, v[q]);
        mx = fmaxf(mx, __shfl_xor_sync(0xFFFFFFFFu, mx, 1));
        float e = 0.f;
#pragma unroll
        for (int q = 0; q < 20; q++) e += __expf(v[q] - mx);
        e += __shfl_xor_sync(0xFFFFFFFFu, e, 1);
        float ls = mx + __logf(e);
        int gn = n0 + node;
        if (gn < NN) {
            float* dst = outp + (size_t)gn * OUTF + half * 20;
#pragma unroll
            for (int q = 0; q < 20; q++) dst[q] = v[q] - ls;
        }
    }
}

// ---------------------------------------------------------------------------
extern "C" void kernel_launch(void* const* d_in, const int* in_sizes, int n_in,
                              void* d_out, int out_size)
{
    const float* x     = (const float*)d_in[0];
    const int*   erow  = (const int*)  d_in[1];
    const int*   ecol  = (const int*)  d_in[2];
    const float* ew    = (const float*)d_in[3];
    const float* W_in  = (const float*)d_in[4];
    const float* b_in  = (const float*)d_in[5];
    const float* c1    = (const float*)d_in[6];
    const float* c2    = (const float*)d_in[7];
    const float* W_out = (const float*)d_in[8];
    float* out = (float*)d_out;

    float *bufA = nullptr, *bufB = nullptr;
    unsigned short *chp = nullptr, *clp = nullptr;
    cudaGetSymbolAddress((void**)&bufA, g_bufA);
    cudaGetSymbolAddress((void**)&bufB, g_bufB);
    cudaGetSymbolAddress((void**)&chp,  g_Ch);
    cudaGetSymbolAddress((void**)&clp,  g_Cl);

    const int SM1 = 2 * 32768 + 32768;   // 96 KB (layer 1, bf16 3-pass)
    const int SM2 = 2 * 16384 + 32768;   // 64 KB (layer 2, fp16 2-pass)
    cudaFuncSetAttribute(kan_mma_kernel<false>,
                         cudaFuncAttributeMaxDynamicSharedMemorySize, SM1);
    cudaFuncSetAttribute(kan_mma_kernel<true>,
                         cudaFuncAttributeMaxDynamicSharedMemorySize, SM2);

    const int kanBlocks  = NNP / 128;          // 782
    const int spmmBlocks = (NN + 7) / 8;
    const size_t cl_sz   = (size_t)16 * 64 * 64;   // entries per layer

    build_csr_kernel<<<NB, 256>>>(erow, ecol, ew, c1, c2);              // 0
    lin_in_kernel<<<NN / 16, 256>>>(x, W_in, b_in);                     // 1
    spmm_csr_kernel<<<spmmBlocks, 256>>>(bufA, bufB);                   // 2
    kan_mma_kernel<false><<<kanBlocks, 256, SM1>>>(
        bufB, chp, clp, bufA, nullptr, nullptr);                        // 3 <- profiled
    spmm_csr_kernel<<<spmmBlocks, 256>>>(bufA, bufB);                   // 4
    kan_mma_kernel<true><<<kanBlocks, 256, SM2>>>(
        bufB, chp + cl_sz, clp + cl_sz, nullptr, W_out, out);           // 5
}

// round 12
// speedup vs baseline: 2.3370x; 1.0218x over previous
#include <cuda_runtime.h>
#include <cuda_bf16.h>
#include <cuda_fp16.h>
#include <math.h>
#include <stdint.h>

#define NN    100000
#define NNP   100096          // padded to multiple of 128
#define NE    1600000
#define INF   128
#define HID   64
#define OUTF  40
#define GRD   8
#define NB    391             // build grid: ceil(NN/256), all co-resident

typedef unsigned long long ull;

// ------------------------- scratch (no cudaMalloc) -------------------------
__device__ float g_bufA[(size_t)NNP * HID];
__device__ float g_bufB[(size_t)NNP * HID];
__device__ int   g_rowstart[NN + 1];
__device__ int   g_cnt[NN];            // zeroed in build phase 3 each replay
__device__ int   g_cur[NN];
__device__ int   g_bsum[NB];
__device__ ull   g_edges[NE];          // packed (w<<32 | col), CSR by row
__device__ int   g_gsync;              // grid barrier counter; reset by lin_in
// 16-bit split coeffs: layer 0 = bf16 hi/lo, layer 1 = fp16 hi/lo
__device__ unsigned short g_Ch[2][16 * 64 * 64];
__device__ unsigned short g_Cl[2][16 * 64 * 64];

// ---------------- f32x2 helpers (spmm / lin_in) ----------------
__device__ __forceinline__ ull pk2(float s) {
    ull d; unsigned u = __float_as_uint(s);
    asm("mov.b64 %0, {%1,%1};" : "=l"(d) : "r"(u));
    return d;
}
__device__ __forceinline__ void fma2(ull& d, ull a, ull b) {
    asm("fma.rn.f32x2 %0, %1, %2, %0;" : "+l"(d) : "l"(a), "l"(b));
}
__device__ __forceinline__ float2 up2(ull v) {
    unsigned lo, hi;
    asm("mov.b64 {%0,%1}, %2;" : "=r"(lo), "=r"(hi) : "l"(v));
    return make_float2(__uint_as_float(lo), __uint_as_float(hi));
}

// ---------------- mma helpers (baseline sm_80+ ISA) ----------------
__device__ __forceinline__ uint32_t smem_u32(const void* p) {
    uint32_t a;
    asm("{ .reg .u64 t; cvta.to.shared.u64 t, %1; cvt.u32.u64 %0, t; }"
        : "=r"(a) : "l"(p));
    return a;
}
__device__ __forceinline__ void ldsm4(uint32_t (&r)[4], uint32_t addr) {
    asm volatile("ldmatrix.sync.aligned.m8n8.x4.shared.b16 {%0,%1,%2,%3}, [%4];"
                 : "=r"(r[0]), "=r"(r[1]), "=r"(r[2]), "=r"(r[3]) : "r"(addr));
}
__device__ __forceinline__ void mma_bf16(float (&d)[4], const uint32_t (&a)[4],
                                         uint32_t b0, uint32_t b1) {
    asm volatile("mma.sync.aligned.m16n8k16.row.col.f32.bf16.bf16.f32 "
                 "{%0,%1,%2,%3}, {%4,%5,%6,%7}, {%8,%9}, {%0,%1,%2,%3};"
                 : "+f"(d[0]), "+f"(d[1]), "+f"(d[2]), "+f"(d[3])
                 : "r"(a[0]), "r"(a[1]), "r"(a[2]), "r"(a[3]),
                   "r"(b0), "r"(b1));
}
__device__ __forceinline__ void mma_f16(float (&d)[4], const uint32_t (&a)[4],
                                        uint32_t b0, uint32_t b1) {
    asm volatile("mma.sync.aligned.m16n8k16.row.col.f32.f16.f16.f32 "
                 "{%0,%1,%2,%3}, {%4,%5,%6,%7}, {%8,%9}, {%0,%1,%2,%3};"
                 : "+f"(d[0]), "+f"(d[1]), "+f"(d[2]), "+f"(d[3])
                 : "r"(a[0]), "r"(a[1]), "r"(a[2]), "r"(a[3]),
                   "r"(b0), "r"(b1));
}
__device__ __forceinline__ void cpasync16(uint32_t dst, const void* src) {
    asm volatile("cp.async.cg.shared.global [%0], [%1], 16;"
                 :: "r"(dst), "l"(src) : "memory");
}
#define CP_COMMIT() asm volatile("cp.async.commit_group;" ::: "memory")
#define CP_WAIT0()  asm volatile("cp.async.wait_group 0;"  ::: "memory")

// ---------------------------------------------------------------------------
// grid barrier for the co-resident build kernel
// ---------------------------------------------------------------------------
__device__ __forceinline__ void gsync(int target)
{
    __threadfence();
    __syncthreads();
    if (threadIdx.x == 0) {
        atomicAdd(&g_gsync, 1);
        volatile int* p = &g_gsync;
        while (*p < target) { }
    }
    __syncthreads();
}

// ---------------------------------------------------------------------------
// Fused CSR build + coeff split prep (layer0: bf16 hi/lo; layer1: fp16 hi/lo)
// ---------------------------------------------------------------------------
__global__ __launch_bounds__(256) void build_csr_kernel(
    const int* __restrict__ erow, const int* __restrict__ ecol,
    const float* __restrict__ ew,
    const float* __restrict__ c1, const float* __restrict__ c2)
{
    __shared__ int sh[256];
    __shared__ int off_sh;
    const int b   = blockIdx.x;
    const int tid = threadIdx.x;
    const int gt  = b * 256 + tid;

    // phase 0a: coeff split
    for (int idx = gt; idx < 2 * 64 * 1024; idx += 256 * NB) {
        int L   = idx >> 16;
        int rem = idx & 65535;
        int j   = rem >> 10;
        int f   = rem & 1023;
        const float* cf = L ? c2 : c1;
        int i = f >> 4, br = (f >> 3) & 1, k = f & 7;
        float v = cf[(((size_t)br * HID + j) * HID + i) * GRD + k];
        unsigned short hb, lb;
        if (L == 0) {
            __nv_bfloat16 vh = __float2bfloat16(v);
            __nv_bfloat16 vl = __float2bfloat16(v - __bfloat162float(vh));
            hb = *reinterpret_cast<unsigned short*>(&vh);
            lb = *reinterpret_cast<unsigned short*>(&vl);
        } else {
            __half vh = __float2half_rn(v);
            __half vl = __float2half_rn(v - __half2float(vh));
            hb = *reinterpret_cast<unsigned short*>(&vh);
            lb = *reinterpret_cast<unsigned short*>(&vl);
        }
        int t = f >> 6, kk = f & 63;
        g_Ch[L][(t * 64 + j) * 64 + kk] = hb;
        g_Cl[L][(t * 64 + j) * 64 + kk] = lb;
    }

    // phase 0b: histogram over rows
    for (int e = gt; e < NE; e += 256 * NB)
        atomicAdd(&g_cnt[erow[e]], 1);
    gsync(NB);

    // phase 1: block-local exclusive scan
    int v = (gt < NN) ? __ldcg(&g_cnt[gt]) : 0;
    sh[tid] = v;
    __syncthreads();
    for (int off = 1; off < 256; off <<= 1) {
        int t = (tid >= off) ? sh[tid - off] : 0;
        __syncthreads();
        if (tid >= off) sh[tid] += t;
        __syncthreads();
    }
    int locpre = sh[tid] - v;
    if (tid == 255) g_bsum[b] = sh[255];
    gsync(2 * NB);

    // phase 2: block offsets; init rowstart + cursors
    if (tid == 0) {
        int s = 0;
        for (int j = 0; j < b; j++) s += __ldcg(&g_bsum[j]);
        off_sh = s;
    }
    __syncthreads();
    if (gt < NN) {
        int rs = off_sh + locpre;
        g_rowstart[gt] = rs;
        g_cur[gt]      = rs;
        if (gt == NN - 1) g_rowstart[NN] = rs + v;
    }
    gsync(3 * NB);

    // phase 3: re-arm counters + scatter edges
    if (gt < NN) g_cnt[gt] = 0;
    for (int e = gt; e < NE; e += 256 * NB) {
        int r = erow[e];
        unsigned c = (unsigned)ecol[e];
        unsigned w = __float_as_uint(ew[e]);
        int pos = atomicAdd(&g_cur[r], 1);
        g_edges[pos] = ((ull)w << 32) | (ull)c;
    }
}

// ---------------------------------------------------------------------------
// CSR spmm: warp per destination row, lane = 2 features, unroll-8 gather.
// ---------------------------------------------------------------------------
__global__ __launch_bounds__(256) void spmm_csr_kernel(
    const float* __restrict__ xin, float* __restrict__ xout)
{
    const int node = blockIdx.x * 8 + (threadIdx.x >> 5);
    const int lane = threadIdx.x & 31;
    if (node >= NN) return;

    const int s = g_rowstart[node];
    const int e = g_rowstart[node + 1];
    const ull* __restrict__ xin2 = reinterpret_cast<const ull*>(xin);

    ull acc = 0ULL;
    int i = s;
    for (; i + 8 <= e; i += 8) {
        ull p0 = __ldg(g_edges + i + 0), p1 = __ldg(g_edges + i + 1);
        ull p2 = __ldg(g_edges + i + 2), p3 = __ldg(g_edges + i + 3);
        ull p4 = __ldg(g_edges + i + 4), p5 = __ldg(g_edges + i + 5);
        ull p6 = __ldg(g_edges + i + 6), p7 = __ldg(g_edges + i + 7);
        ull v0 = __ldg(xin2 + (size_t)(unsigned)p0 * 32 + lane);
        ull v1 = __ldg(xin2 + (size_t)(unsigned)p1 * 32 + lane);
        ull v2 = __ldg(xin2 + (size_t)(unsigned)p2 * 32 + lane);
        ull v3 = __ldg(xin2 + (size_t)(unsigned)p3 * 32 + lane);
        ull v4 = __ldg(xin2 + (size_t)(unsigned)p4 * 32 + lane);
        ull v5 = __ldg(xin2 + (size_t)(unsigned)p5 * 32 + lane);
        ull v6 = __ldg(xin2 + (size_t)(unsigned)p6 * 32 + lane);
        ull v7 = __ldg(xin2 + (size_t)(unsigned)p7 * 32 + lane);
        fma2(acc, pk2(__uint_as_float((unsigned)(p0 >> 32))), v0);
        fma2(acc, pk2(__uint_as_float((unsigned)(p1 >> 32))), v1);
        fma2(acc, pk2(__uint_as_float((unsigned)(p2 >> 32))), v2);
        fma2(acc, pk2(__uint_as_float((unsigned)(p3 >> 32))), v3);
        fma2(acc, pk2(__uint_as_float((unsigned)(p4 >> 32))), v4);
        fma2(acc, pk2(__uint_as_float((unsigned)(p5 >> 32))), v5);
        fma2(acc, pk2(__uint_as_float((unsigned)(p6 >> 32))), v6);
        fma2(acc, pk2(__uint_as_float((unsigned)(p7 >> 32))), v7);
    }
    for (; i + 2 <= e; i += 2) {
        ull p0 = __ldg(g_edges + i + 0), p1 = __ldg(g_edges + i + 1);
        ull v0 = __ldg(xin2 + (size_t)(unsigned)p0 * 32 + lane);
        ull v1 = __ldg(xin2 + (size_t)(unsigned)p1 * 32 + lane);
        fma2(acc, pk2(__uint_as_float((unsigned)(p0 >> 32))), v0);
        fma2(acc, pk2(__uint_as_float((unsigned)(p1 >> 32))), v1);
    }
    if (i < e) {
        ull p = __ldg(g_edges + i);
        ull v = __ldg(xin2 + (size_t)(unsigned)p * 32 + lane);
        fma2(acc, pk2(__uint_as_float((unsigned)(p >> 32))), v);
    }
    reinterpret_cast<ull*>(xout)[(size_t)node * 32 + lane] = acc;
}

// ---------------------------------------------------------------------------
// h = x @ W_in + b_in -> bufA.  Also resets the build grid-barrier counter.
// ---------------------------------------------------------------------------
__global__ __launch_bounds__(256) void lin_in_kernel(
    const float* __restrict__ x, const float* __restrict__ W,
    const float* __restrict__ b)
{
    if (blockIdx.x == 0 && threadIdx.x == 0) g_gsync = 0;

    __shared__ float xs[16][INF];
    __shared__ float ws[INF * HID];
    const int n0  = blockIdx.x * 16;
    const int tid = threadIdx.x;

    for (int idx = tid; idx < INF * HID / 4; idx += 256)
        reinterpret_cast<float4*>(ws)[idx] =
            reinterpret_cast<const float4*>(W)[idx];
    for (int idx = tid; idx < 16 * INF; idx += 256) {
        int n = idx >> 7, c = idx & 127;
        xs[n][c] = x[(size_t)(n0 + n) * INF + c];
    }
    __syncthreads();

    const int j4 = (tid & 15) * 4;
    const int ny = tid >> 4;
    const int n  = n0 + ny;

    ull a01 = 0ULL, a23 = 0ULL;
#pragma unroll 8
    for (int i = 0; i < INF; i++) {
        ull xv = pk2(xs[ny][i]);
        const ull* w2 = reinterpret_cast<const ull*>(ws + i * HID + j4);
        fma2(a01, xv, w2[0]);
        fma2(a23, xv, w2[1]);
    }
    float2 v01 = up2(a01), v23 = up2(a23);
    *reinterpret_cast<float4*>(g_bufA + (size_t)n * HID + j4) =
        make_float4(v01.x + b[j4], v01.y + b[j4 + 1],
                    v23.x + b[j4 + 2], v23.y + b[j4 + 3]);
}

// ---------------------------------------------------------------------------
// KAN layer v4: warp-specialized producer/consumer pipeline.
// 384 threads: warps 0-7 = consumers (pure LDSM+MMA), warps 8-11 = producers
// (featgen + coeff cp.async). One __syncthreads per tile; producers build
// tile t+1 into buffer b^1 while consumers mma tile t from buffer b.
// !FUSED (layer 1): bf16 3-pass, 96 KB smem.
//  FUSED (layer 2): fp16 2-pass, 64 KB smem + fused lin_out/log_softmax.
// ---------------------------------------------------------------------------
template<bool FUSED>
__global__ __launch_bounds__(384, 2) void kan_mma_kernel(
    const float* __restrict__ xin,
    const unsigned short* __restrict__ Ch,
    const unsigned short* __restrict__ Cl,
    float* __restrict__ xout,
    const float* __restrict__ Wout,
    float* __restrict__ outp)
{
    constexpr int FB     = FUSED ? 16384 : 32768;
    constexpr int CB_OFF = 2 * FB;

    extern __shared__ char sm[];
    const int tid   = threadIdx.x;
    const int lane  = tid & 31;
    const int wid   = tid >> 5;
    const bool producer = (wid >= 8);
    const int n0    = blockIdx.x * 128;
    const uint32_t sbase = smem_u32(sm);

    // consumer tiling
    const int warpM = wid & 3;
    const int warpN = (wid >> 2) & 1;
    const int sel  = lane >> 3;
    const int lrow = lane & 7;

    const char* ChB = reinterpret_cast<const char*>(Ch);
    const char* ClB = reinterpret_cast<const char*>(Cl);

    const int ptid = tid - 256;        // producer thread id 0..127 (node)

    // ---- producer: featgen for tile tt into fbuf[bsel] (4 ii per thread) ----
    auto featgen = [&](int tt, int bsel) {
        char* fb = sm + bsel * FB;
        const int fn = ptid;
        uint32_t rowoff = (uint32_t)fn * 128;
#pragma unroll
        for (int ii = 0; ii < 4; ii++) {
            float xv = __ldg(xin + (size_t)(n0 + fn) * HID + tt * 4 + ii);
            float s1, c1;
            __sincosf(xv, &s1, &c1);
            float cc[8], ss[8];
            cc[0] = c1; ss[0] = s1;
            float tw = 2.f * c1;
            float cm2 = 1.f, cm1 = c1, sm2 = 0.f, sm1 = s1;
#pragma unroll
            for (int k = 1; k < 8; k++) {
                float cn = tw * cm1 - cm2;
                float sn = tw * sm1 - sm2;
                cc[k] = cn; ss[k] = sn;
                cm2 = cm1; cm1 = cn; sm2 = sm1; sm1 = sn;
            }
            uint32_t cchunk = (uint32_t)((2 * ii)     ^ (fn & 7)) * 16;
            uint32_t schunk = (uint32_t)((2 * ii + 1) ^ (fn & 7)) * 16;
            if (FUSED) {
                uint32_t ph[4], psn[4];
#pragma unroll
                for (int m = 0; m < 4; m++) {
                    __half2 h2 = __floats2half2_rn(cc[2*m], cc[2*m+1]);
                    ph[m] = *reinterpret_cast<uint32_t*>(&h2);
                    h2 = __floats2half2_rn(ss[2*m], ss[2*m+1]);
                    psn[m] = *reinterpret_cast<uint32_t*>(&h2);
                }
                *reinterpret_cast<uint4*>(fb + rowoff + cchunk) =
                    make_uint4(ph[0], ph[1], ph[2], ph[3]);
                *reinterpret_cast<uint4*>(fb + rowoff + schunk) =
                    make_uint4(psn[0], psn[1], psn[2], psn[3]);
            } else {
                uint32_t chh[4], chl[4], shh[4], shl[4];
#pragma unroll
                for (int m = 0; m < 4; m++) {
                    __nv_bfloat162 h2 = __floats2bfloat162_rn(cc[2*m], cc[2*m+1]);
                    __nv_bfloat162 l2 = __floats2bfloat162_rn(
                        cc[2*m]   - __bfloat162float(h2.x),
                        cc[2*m+1] - __bfloat162float(h2.y));
                    chh[m] = *reinterpret_cast<uint32_t*>(&h2);
                    chl[m] = *reinterpret_cast<uint32_t*>(&l2);
                    h2 = __floats2bfloat162_rn(ss[2*m], ss[2*m+1]);
                    l2 = __floats2bfloat162_rn(
                        ss[2*m]   - __bfloat162float(h2.x),
                        ss[2*m+1] - __bfloat162float(h2.y));
                    shh[m] = *reinterpret_cast<uint32_t*>(&h2);
                    shl[m] = *reinterpret_cast<uint32_t*>(&l2);
                }
                *reinterpret_cast<uint4*>(fb + rowoff + cchunk) =
                    make_uint4(chh[0], chh[1], chh[2], chh[3]);
                *reinterpret_cast<uint4*>(fb + rowoff + schunk) =
                    make_uint4(shh[0], shh[1], shh[2], shh[3]);
                *reinterpret_cast<uint4*>(fb + 16384 + rowoff + cchunk) =
                    make_uint4(chl[0], chl[1], chl[2], chl[3]);
                *reinterpret_cast<uint4*>(fb + 16384 + rowoff + schunk) =
                    make_uint4(shl[0], shl[1], shl[2], shl[3]);
            }
        }
    };

    // ---- producer: cp.async coeff tile tt into cbuf[bsel] (8 per thread) ----
    auto coeff_cp = [&](int tt, int bsel) {
#pragma unroll
        for (int r = 0; r < 8; r++) {
            int idx = ptid + 128 * r;
            int mat = idx >> 9, rem = idx & 511;
            int j = rem >> 3, c = rem & 7;
            uint32_t dst = sbase + CB_OFF + bsel * 16384 + mat * 8192
                         + j * 128 + ((c ^ (j & 7)) * 16);
            const char* src = (mat ? ClB : ChB)
                            + ((size_t)tt * 64 + j) * 128 + c * 16;
            cpasync16(dst, src);
        }
        CP_COMMIT();
    };

    float acc[2][4][4];
#pragma unroll
    for (int m = 0; m < 2; m++)
#pragma unroll
        for (int nt = 0; nt < 4; nt++)
#pragma unroll
            for (int q = 0; q < 4; q++) acc[m][nt][q] = 0.f;

    // preloop: producers stage tile 0 into buffer 0
    if (producer) {
        coeff_cp(0, 0);
        featgen(0, 0);
        CP_WAIT0();
    }

    for (int t = 0; t < 16; t++) {
        const int buf = t & 1;
        __syncthreads();   // fbuf/cbuf[buf] published; fbuf/cbuf[buf^1] free

        if (producer) {
            if (t + 1 < 16) {
                coeff_cp(t + 1, buf ^ 1);
                featgen(t + 1, buf ^ 1);
                CP_WAIT0();
            }
        } else {
            // ---- mma(t) from fbuf[buf], cbuf[buf] ----
            const uint32_t fbb = sbase + (uint32_t)buf * FB;
            const uint32_t cbb = sbase + CB_OFF + (uint32_t)buf * 16384;
#pragma unroll
            for (int ks = 0; ks < 4; ks++) {
                uint32_t ah[2][4], al[2][4];
#pragma unroll
                for (int m = 0; m < 2; m++) {
                    uint32_t rowA = (uint32_t)(warpM * 32 + m * 16 + lrow + (sel & 1) * 8);
                    uint32_t ca   = (uint32_t)((2 * ks + (sel >> 1)) ^ lrow) * 16;
                    uint32_t ra   = fbb + rowA * 128 + ca;
                    ldsm4(ah[m], ra);
                    if (!FUSED) ldsm4(al[m], ra + 16384);
                }
#pragma unroll
                for (int pi = 0; pi < 2; pi++) {
                    uint32_t rowB = (uint32_t)(warpN * 32 + pi * 16 + lrow + (sel >> 1) * 8);
                    uint32_t cb   = (uint32_t)((2 * ks + (sel & 1)) ^ lrow) * 16;
                    uint32_t rb   = cbb + rowB * 128 + cb;
                    uint32_t bh[4], bl[4];
                    ldsm4(bh, rb);
                    ldsm4(bl, rb + 8192);
#pragma unroll
                    for (int ntl = 0; ntl < 2; ntl++) {
                        uint32_t b0h = bh[ntl * 2], b1h = bh[ntl * 2 + 1];
                        uint32_t b0l = bl[ntl * 2], b1l = bl[ntl * 2 + 1];
                        int nt = pi * 2 + ntl;
#pragma unroll
                        for (int m = 0; m < 2; m++) {
                            if (FUSED) {
                                mma_f16(acc[m][nt], ah[m], b0h, b1h);
                                mma_f16(acc[m][nt], ah[m], b0l, b1l);
                            } else {
                                mma_bf16(acc[m][nt], ah[m], b0h, b1h);
                                mma_bf16(acc[m][nt], al[m], b0h, b1h);
                                mma_bf16(acc[m][nt], ah[m], b0l, b1l);
                            }
                        }
                    }
                }
            }
        }
    }

    const int g2 = lane >> 2, c4 = lane & 3;

    if (!FUSED) {
        if (!producer) {
#pragma unroll
            for (int m = 0; m < 2; m++) {
#pragma unroll
                for (int nt = 0; nt < 4; nt++) {
                    int row0 = n0 + warpM * 32 + m * 16 + g2;
                    int col  = warpN * 32 + nt * 8 + c4 * 2;
                    *reinterpret_cast<float2*>(xout + (size_t)row0 * HID + col) =
                        make_float2(acc[m][nt][0], acc[m][nt][1]);
                    *reinterpret_cast<float2*>(xout + (size_t)(row0 + 8) * HID + col) =
                        make_float2(acc[m][nt][2], acc[m][nt][3]);
                }
            }
        }
    } else {
        // fused lin_out + log_softmax epilogue
        __syncthreads();               // all mma reads of smem done
        float* hsm = reinterpret_cast<float*>(sm);          // [128][66]
        float* wsm = reinterpret_cast<float*>(sm + 33792);  // [64][40]
        for (int q = tid; q < HID * OUTF; q += 384) wsm[q] = Wout[q];
        if (!producer) {
#pragma unroll
            for (int m = 0; m < 2; m++) {
#pragma unroll
                for (int nt = 0; nt < 4; nt++) {
                    int row = warpM * 32 + m * 16 + g2;
                    int col = warpN * 32 + nt * 8 + c4 * 2;
                    *reinterpret_cast<float2*>(hsm + row * 66 + col) =
                        make_float2(acc[m][nt][0], acc[m][nt][1]);
                    *reinterpret_cast<float2*>(hsm + (row + 8) * 66 + col) =
                        make_float2(acc[m][nt][2], acc[m][nt][3]);
                }
            }
        }
        __syncthreads();

        if (tid < 256) {
            const int node = tid >> 1;
            const int half = tid & 1;
            float v[20];
#pragma unroll
            for (int q = 0; q < 20; q++) v[q] = 0.f;
#pragma unroll 8
            for (int i = 0; i < HID; i++) {
                float h = hsm[node * 66 + i];
                const float4* wr = reinterpret_cast<const float4*>(
                    wsm + i * OUTF + half * 20);
#pragma unroll
                for (int q = 0; q < 5; q++) {
                    float4 w = wr[q];
                    v[4*q+0] += h * w.x; v[4*q+1] += h * w.y;
                    v[4*q+2] += h * w.z; v[4*q+3] += h * w.w;
                }
            }
            float mx = v[0];
#pragma unroll
            for (int q = 1; q < 20; q++) mx = fmaxf(mx, v[q]);
            mx = fmaxf(mx, __shfl_xor_sync(0xFFFFFFFFu, mx, 1));
            float e = 0.f;
#pragma unroll
            for (int q = 0; q < 20; q++) e += __expf(v[q] - mx);
            e += __shfl_xor_sync(0xFFFFFFFFu, e, 1);
            float ls = mx + __logf(e);
            int gn = n0 + node;
            if (gn < NN) {
                float* dst = outp + (size_t)gn * OUTF + half * 20;
#pragma unroll
                for (int q = 0; q < 20; q++) dst[q] = v[q] - ls;
            }
        }
    }
}

// ---------------------------------------------------------------------------
extern "C" void kernel_launch(void* const* d_in, const int* in_sizes, int n_in,
                              void* d_out, int out_size)
{
    const float* x     = (const float*)d_in[0];
    const int*   erow  = (const int*)  d_in[1];
    const int*   ecol  = (const int*)  d_in[2];
    const float* ew    = (const float*)d_in[3];
    const float* W_in  = (const float*)d_in[4];
    const float* b_in  = (const float*)d_in[5];
    const float* c1    = (const float*)d_in[6];
    const float* c2    = (const float*)d_in[7];
    const float* W_out = (const float*)d_in[8];
    float* out = (float*)d_out;

    float *bufA = nullptr, *bufB = nullptr;
    unsigned short *chp = nullptr, *clp = nullptr;
    cudaGetSymbolAddress((void**)&bufA, g_bufA);
    cudaGetSymbolAddress((void**)&bufB, g_bufB);
    cudaGetSymbolAddress((void**)&chp,  g_Ch);
    cudaGetSymbolAddress((void**)&clp,  g_Cl);

    const int SM1 = 2 * 32768 + 32768;   // 96 KB (layer 1, bf16 3-pass)
    const int SM2 = 2 * 16384 + 32768;   // 64 KB (layer 2, fp16 2-pass)
    cudaFuncSetAttribute(kan_mma_kernel<false>,
                         cudaFuncAttributeMaxDynamicSharedMemorySize, SM1);
    cudaFuncSetAttribute(kan_mma_kernel<true>,
                         cudaFuncAttributeMaxDynamicSharedMemorySize, SM2);

    const int kanBlocks  = NNP / 128;          // 782
    const int spmmBlocks = (NN + 7) / 8;
    const size_t cl_sz   = (size_t)16 * 64 * 64;   // entries per layer

    build_csr_kernel<<<NB, 256>>>(erow, ecol, ew, c1, c2);              // 0
    lin_in_kernel<<<NN / 16, 256>>>(x, W_in, b_in);                     // 1
    spmm_csr_kernel<<<spmmBlocks, 256>>>(bufA, bufB);                   // 2
    kan_mma_kernel<false><<<kanBlocks, 384, SM1>>>(
        bufB, chp, clp, bufA, nullptr, nullptr);                        // 3 <- profiled
    spmm_csr_kernel<<<spmmBlocks, 256>>>(bufA, bufB);                   // 4
    kan_mma_kernel<true><<<kanBlocks, 384, SM2>>>(
        bufB, chp + cl_sz, clp + cl_sz, nullptr, W_out, out);           // 5
}

// round 13
// speedup vs baseline: 2.5569x; 1.0941x over previous
#include <cuda_runtime.h>
#include <cuda_bf16.h>
#include <cuda_fp16.h>
#include <math.h>
#include <stdint.h>

#define NN    100000
#define NNP   100096          // padded to multiple of 128
#define NE    1600000
#define INF   128
#define HID   64
#define OUTF  40
#define GRD   8
#define NB    391             // build grid: ceil(NN/256), all co-resident

typedef unsigned long long ull;

// ------------------------- scratch (no cudaMalloc) -------------------------
__device__ float g_bufA[(size_t)NNP * HID];
__device__ float g_bufB[(size_t)NNP * HID];
__device__ int   g_rowstart[NN + 1];
__device__ int   g_cnt[NN];            // zeroed in build phase 3 each replay
__device__ int   g_cur[NN];
__device__ int   g_bsum[NB];
__device__ ull   g_edges[NE];          // packed (w<<32 | col), CSR by row
__device__ int   g_gsync;              // grid barrier counter; reset by lin_in
// fp16 hi/lo split coeffs: [layer][tile 0..15][j 0..63][kk 0..63]
__device__ unsigned short g_Ch[2][16 * 64 * 64];
__device__ unsigned short g_Cl[2][16 * 64 * 64];

// ---------------- f32x2 helpers (spmm / lin_in) ----------------
__device__ __forceinline__ ull pk2(float s) {
    ull d; unsigned u = __float_as_uint(s);
    asm("mov.b64 %0, {%1,%1};" : "=l"(d) : "r"(u));
    return d;
}
__device__ __forceinline__ void fma2(ull& d, ull a, ull b) {
    asm("fma.rn.f32x2 %0, %1, %2, %0;" : "+l"(d) : "l"(a), "l"(b));
}
__device__ __forceinline__ float2 up2(ull v) {
    unsigned lo, hi;
    asm("mov.b64 {%0,%1}, %2;" : "=r"(lo), "=r"(hi) : "l"(v));
    return make_float2(__uint_as_float(lo), __uint_as_float(hi));
}

// ---------------- mma helpers (baseline sm_80+ ISA) ----------------
__device__ __forceinline__ uint32_t smem_u32(const void* p) {
    uint32_t a;
    asm("{ .reg .u64 t; cvta.to.shared.u64 t, %1; cvt.u32.u64 %0, t; }"
        : "=r"(a) : "l"(p));
    return a;
}
__device__ __forceinline__ void ldsm4(uint32_t (&r)[4], uint32_t addr) {
    asm volatile("ldmatrix.sync.aligned.m8n8.x4.shared.b16 {%0,%1,%2,%3}, [%4];"
                 : "=r"(r[0]), "=r"(r[1]), "=r"(r[2]), "=r"(r[3]) : "r"(addr));
}
__device__ __forceinline__ void mma_f16(float (&d)[4], const uint32_t (&a)[4],
                                        uint32_t b0, uint32_t b1) {
    asm volatile("mma.sync.aligned.m16n8k16.row.col.f32.f16.f16.f32 "
                 "{%0,%1,%2,%3}, {%4,%5,%6,%7}, {%8,%9}, {%0,%1,%2,%3};"
                 : "+f"(d[0]), "+f"(d[1]), "+f"(d[2]), "+f"(d[3])
                 : "r"(a[0]), "r"(a[1]), "r"(a[2]), "r"(a[3]),
                   "r"(b0), "r"(b1));
}
__device__ __forceinline__ void cpasync16(uint32_t dst, const void* src) {
    asm volatile("cp.async.cg.shared.global [%0], [%1], 16;"
                 :: "r"(dst), "l"(src) : "memory");
}
#define CP_COMMIT() asm volatile("cp.async.commit_group;" ::: "memory")
#define CP_WAIT0()  asm volatile("cp.async.wait_group 0;"  ::: "memory")

// ---------------------------------------------------------------------------
// grid barrier for the co-resident build kernel (nanosleep backoff poll)
// ---------------------------------------------------------------------------
__device__ __forceinline__ void gsync(int target)
{
    __threadfence();
    __syncthreads();
    if (threadIdx.x == 0) {
        atomicAdd(&g_gsync, 1);
        volatile int* p = &g_gsync;
        while (*p < target) __nanosleep(64);
    }
    __syncthreads();
}

// ---------------------------------------------------------------------------
// Fused CSR build + coeff fp16 hi/lo prep.  Parallel offset scan in phase 2.
// ---------------------------------------------------------------------------
__global__ __launch_bounds__(256) void build_csr_kernel(
    const int* __restrict__ erow, const int* __restrict__ ecol,
    const float* __restrict__ ew,
    const float* __restrict__ c1, const float* __restrict__ c2)
{
    __shared__ int sh[256];
    __shared__ int bs2[NB + 1];
    const int b   = blockIdx.x;
    const int tid = threadIdx.x;
    const int gt  = b * 256 + tid;

    // phase 0a: coeff split (fp16 hi/lo, both layers)
    for (int idx = gt; idx < 2 * 64 * 1024; idx += 256 * NB) {
        int L   = idx >> 16;
        int rem = idx & 65535;
        int j   = rem >> 10;
        int f   = rem & 1023;
        const float* cf = L ? c2 : c1;
        int i = f >> 4, br = (f >> 3) & 1, k = f & 7;
        float v = cf[(((size_t)br * HID + j) * HID + i) * GRD + k];
        __half vh = __float2half_rn(v);
        __half vl = __float2half_rn(v - __half2float(vh));
        int t = f >> 6, kk = f & 63;
        g_Ch[L][(t * 64 + j) * 64 + kk] = *reinterpret_cast<unsigned short*>(&vh);
        g_Cl[L][(t * 64 + j) * 64 + kk] = *reinterpret_cast<unsigned short*>(&vl);
    }

    // phase 0b: histogram over rows
    for (int e = gt; e < NE; e += 256 * NB)
        atomicAdd(&g_cnt[erow[e]], 1);
    gsync(NB);

    // phase 1: block-local exclusive scan of counts
    int v = (gt < NN) ? __ldcg(&g_cnt[gt]) : 0;
    sh[tid] = v;
    __syncthreads();
    for (int off = 1; off < 256; off <<= 1) {
        int t = (tid >= off) ? sh[tid - off] : 0;
        __syncthreads();
        if (tid >= off) sh[tid] += t;
        __syncthreads();
    }
    int locpre = sh[tid] - v;
    if (tid == 255) g_bsum[b] = sh[255];
    gsync(2 * NB);

    // phase 2: cooperative scan of block sums (every block, in shared)
    for (int j = tid; j < NB; j += 256) bs2[j] = __ldcg(&g_bsum[j]);
    __syncthreads();
    for (int off = 1; off < NB; off <<= 1) {
        int t1 = 0, t2 = 0;
        int i2 = tid + 256;
        if (tid >= off && tid < NB) t1 = bs2[tid - off];
        if (i2  >= off && i2  < NB) t2 = bs2[i2 - off];
        __syncthreads();
        if (tid >= off && tid < NB) bs2[tid] += t1;
        if (i2  >= off && i2  < NB) bs2[i2]  += t2;
        __syncthreads();
    }
    const int off_b = (b == 0) ? 0 : bs2[b - 1];   // exclusive offset for block b
    if (gt < NN) {
        int rs = off_b + locpre;
        g_rowstart[gt] = rs;
        g_cur[gt]      = rs;
        if (gt == NN - 1) g_rowstart[NN] = rs + v;
    }
    gsync(3 * NB);

    // phase 3: re-arm counters + scatter edges
    if (gt < NN) g_cnt[gt] = 0;
    for (int e = gt; e < NE; e += 256 * NB) {
        int r = erow[e];
        unsigned c = (unsigned)ecol[e];
        unsigned w = __float_as_uint(ew[e]);
        int pos = atomicAdd(&g_cur[r], 1);
        g_edges[pos] = ((ull)w << 32) | (ull)c;
    }
}

// ---------------------------------------------------------------------------
// CSR spmm: warp per destination row, lane = 2 features, unroll-8 gather.
// ---------------------------------------------------------------------------
__global__ __launch_bounds__(256) void spmm_csr_kernel(
    const float* __restrict__ xin, float* __restrict__ xout)
{
    const int node = blockIdx.x * 8 + (threadIdx.x >> 5);
    const int lane = threadIdx.x & 31;
    if (node >= NN) return;

    const int s = g_rowstart[node];
    const int e = g_rowstart[node + 1];
    const ull* __restrict__ xin2 = reinterpret_cast<const ull*>(xin);

    ull acc = 0ULL;
    int i = s;
    for (; i + 8 <= e; i += 8) {
        ull p0 = __ldg(g_edges + i + 0), p1 = __ldg(g_edges + i + 1);
        ull p2 = __ldg(g_edges + i + 2), p3 = __ldg(g_edges + i + 3);
        ull p4 = __ldg(g_edges + i + 4), p5 = __ldg(g_edges + i + 5);
        ull p6 = __ldg(g_edges + i + 6), p7 = __ldg(g_edges + i + 7);
        ull v0 = __ldg(xin2 + (size_t)(unsigned)p0 * 32 + lane);
        ull v1 = __ldg(xin2 + (size_t)(unsigned)p1 * 32 + lane);
        ull v2 = __ldg(xin2 + (size_t)(unsigned)p2 * 32 + lane);
        ull v3 = __ldg(xin2 + (size_t)(unsigned)p3 * 32 + lane);
        ull v4 = __ldg(xin2 + (size_t)(unsigned)p4 * 32 + lane);
        ull v5 = __ldg(xin2 + (size_t)(unsigned)p5 * 32 + lane);
        ull v6 = __ldg(xin2 + (size_t)(unsigned)p6 * 32 + lane);
        ull v7 = __ldg(xin2 + (size_t)(unsigned)p7 * 32 + lane);
        fma2(acc, pk2(__uint_as_float((unsigned)(p0 >> 32))), v0);
        fma2(acc, pk2(__uint_as_float((unsigned)(p1 >> 32))), v1);
        fma2(acc, pk2(__uint_as_float((unsigned)(p2 >> 32))), v2);
        fma2(acc, pk2(__uint_as_float((unsigned)(p3 >> 32))), v3);
        fma2(acc, pk2(__uint_as_float((unsigned)(p4 >> 32))), v4);
        fma2(acc, pk2(__uint_as_float((unsigned)(p5 >> 32))), v5);
        fma2(acc, pk2(__uint_as_float((unsigned)(p6 >> 32))), v6);
        fma2(acc, pk2(__uint_as_float((unsigned)(p7 >> 32))), v7);
    }
    for (; i + 2 <= e; i += 2) {
        ull p0 = __ldg(g_edges + i + 0), p1 = __ldg(g_edges + i + 1);
        ull v0 = __ldg(xin2 + (size_t)(unsigned)p0 * 32 + lane);
        ull v1 = __ldg(xin2 + (size_t)(unsigned)p1 * 32 + lane);
        fma2(acc, pk2(__uint_as_float((unsigned)(p0 >> 32))), v0);
        fma2(acc, pk2(__uint_as_float((unsigned)(p1 >> 32))), v1);
    }
    if (i < e) {
        ull p = __ldg(g_edges + i);
        ull v = __ldg(xin2 + (size_t)(unsigned)p * 32 + lane);
        fma2(acc, pk2(__uint_as_float((unsigned)(p >> 32))), v);
    }
    reinterpret_cast<ull*>(xout)[(size_t)node * 32 + lane] = acc;
}

// ---------------------------------------------------------------------------
// h = x @ W_in + b_in -> bufA.  Also resets the build grid-barrier counter.
// ---------------------------------------------------------------------------
__global__ __launch_bounds__(256) void lin_in_kernel(
    const float* __restrict__ x, const float* __restrict__ W,
    const float* __restrict__ b)
{
    if (blockIdx.x == 0 && threadIdx.x == 0) g_gsync = 0;

    __shared__ float xs[16][INF];
    __shared__ float ws[INF * HID];
    const int n0  = blockIdx.x * 16;
    const int tid = threadIdx.x;

    for (int idx = tid; idx < INF * HID / 4; idx += 256)
        reinterpret_cast<float4*>(ws)[idx] =
            reinterpret_cast<const float4*>(W)[idx];
    for (int idx = tid; idx < 16 * INF; idx += 256) {
        int n = idx >> 7, c = idx & 127;
        xs[n][c] = x[(size_t)(n0 + n) * INF + c];
    }
    __syncthreads();

    const int j4 = (tid & 15) * 4;
    const int ny = tid >> 4;
    const int n  = n0 + ny;

    ull a01 = 0ULL, a23 = 0ULL;
#pragma unroll 8
    for (int i = 0; i < INF; i++) {
        ull xv = pk2(xs[ny][i]);
        const ull* w2 = reinterpret_cast<const ull*>(ws + i * HID + j4);
        fma2(a01, xv, w2[0]);
        fma2(a23, xv, w2[1]);
    }
    float2 v01 = up2(a01), v23 = up2(a23);
    *reinterpret_cast<float4*>(g_bufA + (size_t)n * HID + j4) =
        make_float4(v01.x + b[j4], v01.y + b[j4 + 1],
                    v23.x + b[j4 + 2], v23.y + b[j4 + 3]);
}

// ---------------------------------------------------------------------------
// KAN layer v5: warp-specialized pipeline, fp16 2-pass BOTH layers.
// 384 threads: warps 0-7 consumers (LDSM+MMA), warps 8-11 producers
// (featgen fp16 + coeff cp.async). 64 KB smem.
// FUSED adds the lin_out + log_softmax epilogue.
// smem: fbuf[2] @0/@16384 (fp16 features), cbuf[2] @32768 (hi @0, lo @8192).
// ---------------------------------------------------------------------------
#define FB      16384
#define CB_OFF  32768
#define KAN_SMEM 65536

template<bool FUSED>
__global__ __launch_bounds__(384, 2) void kan_mma_kernel(
    const float* __restrict__ xin,
    const unsigned short* __restrict__ Ch,
    const unsigned short* __restrict__ Cl,
    float* __restrict__ xout,
    const float* __restrict__ Wout,
    float* __restrict__ outp)
{
    extern __shared__ char sm[];
    const int tid   = threadIdx.x;
    const int lane  = tid & 31;
    const int wid   = tid >> 5;
    const bool producer = (wid >= 8);
    const int n0    = blockIdx.x * 128;
    const uint32_t sbase = smem_u32(sm);

    const int warpM = wid & 3;
    const int warpN = (wid >> 2) & 1;
    const int sel  = lane >> 3;
    const int lrow = lane & 7;

    const char* ChB = reinterpret_cast<const char*>(Ch);
    const char* ClB = reinterpret_cast<const char*>(Cl);

    const int ptid = tid - 256;        // producer thread id 0..127 (node)

    auto featgen = [&](int tt, int bsel) {
        char* fb = sm + bsel * FB;
        const int fn = ptid;
        uint32_t rowoff = (uint32_t)fn * 128;
#pragma unroll
        for (int ii = 0; ii < 4; ii++) {
            float xv = __ldg(xin + (size_t)(n0 + fn) * HID + tt * 4 + ii);
            float s1, c1;
            __sincosf(xv, &s1, &c1);
            float cc[8], ss[8];
            cc[0] = c1; ss[0] = s1;
            float tw = 2.f * c1;
            float cm2 = 1.f, cm1 = c1, sm2 = 0.f, sm1 = s1;
#pragma unroll
            for (int k = 1; k < 8; k++) {
                float cn = tw * cm1 - cm2;
                float sn = tw * sm1 - sm2;
                cc[k] = cn; ss[k] = sn;
                cm2 = cm1; cm1 = cn; sm2 = sm1; sm1 = sn;
            }
            uint32_t ph[4], psn[4];
#pragma unroll
            for (int m = 0; m < 4; m++) {
                __half2 h2 = __floats2half2_rn(cc[2*m], cc[2*m+1]);
                ph[m] = *reinterpret_cast<uint32_t*>(&h2);
                h2 = __floats2half2_rn(ss[2*m], ss[2*m+1]);
                psn[m] = *reinterpret_cast<uint32_t*>(&h2);
            }
            uint32_t cchunk = (uint32_t)((2 * ii)     ^ (fn & 7)) * 16;
            uint32_t schunk = (uint32_t)((2 * ii + 1) ^ (fn & 7)) * 16;
            *reinterpret_cast<uint4*>(fb + rowoff + cchunk) =
                make_uint4(ph[0], ph[1], ph[2], ph[3]);
            *reinterpret_cast<uint4*>(fb + rowoff + schunk) =
                make_uint4(psn[0], psn[1], psn[2], psn[3]);
        }
    };

    auto coeff_cp = [&](int tt, int bsel) {
#pragma unroll
        for (int r = 0; r < 8; r++) {
            int idx = ptid + 128 * r;
            int mat = idx >> 9, rem = idx & 511;
            int j = rem >> 3, c = rem & 7;
            uint32_t dst = sbase + CB_OFF + bsel * 16384 + mat * 8192
                         + j * 128 + ((c ^ (j & 7)) * 16);
            const char* src = (mat ? ClB : ChB)
                            + ((size_t)tt * 64 + j) * 128 + c * 16;
            cpasync16(dst, src);
        }
        CP_COMMIT();
    };

    float acc[2][4][4];
#pragma unroll
    for (int m = 0; m < 2; m++)
#pragma unroll
        for (int nt = 0; nt < 4; nt++)
#pragma unroll
            for (int q = 0; q < 4; q++) acc[m][nt][q] = 0.f;

    if (producer) {
        coeff_cp(0, 0);
        featgen(0, 0);
        CP_WAIT0();
    }

    for (int t = 0; t < 16; t++) {
        const int buf = t & 1;
        __syncthreads();   // fbuf/cbuf[buf] published; [buf^1] free

        if (producer) {
            if (t + 1 < 16) {
                coeff_cp(t + 1, buf ^ 1);
                featgen(t + 1, buf ^ 1);
                CP_WAIT0();
            }
        } else {
            const uint32_t fbb = sbase + (uint32_t)buf * FB;
            const uint32_t cbb = sbase + CB_OFF + (uint32_t)buf * 16384;
#pragma unroll
            for (int ks = 0; ks < 4; ks++) {
                uint32_t ah[2][4];
#pragma unroll
                for (int m = 0; m < 2; m++) {
                    uint32_t rowA = (uint32_t)(warpM * 32 + m * 16 + lrow + (sel & 1) * 8);
                    uint32_t ca   = (uint32_t)((2 * ks + (sel >> 1)) ^ lrow) * 16;
                    ldsm4(ah[m], fbb + rowA * 128 + ca);
                }
#pragma unroll
                for (int pi = 0; pi < 2; pi++) {
                    uint32_t rowB = (uint32_t)(warpN * 32 + pi * 16 + lrow + (sel >> 1) * 8);
                    uint32_t cb   = (uint32_t)((2 * ks + (sel & 1)) ^ lrow) * 16;
                    uint32_t rb   = cbb + rowB * 128 + cb;
                    uint32_t bh[4], bl[4];
                    ldsm4(bh, rb);
                    ldsm4(bl, rb + 8192);
#pragma unroll
                    for (int ntl = 0; ntl < 2; ntl++) {
                        uint32_t b0h = bh[ntl * 2], b1h = bh[ntl * 2 + 1];
                        uint32_t b0l = bl[ntl * 2], b1l = bl[ntl * 2 + 1];
                        int nt = pi * 2 + ntl;
#pragma unroll
                        for (int m = 0; m < 2; m++) {
                            mma_f16(acc[m][nt], ah[m], b0h, b1h);
                            mma_f16(acc[m][nt], ah[m], b0l, b1l);
                        }
                    }
                }
            }
        }
    }

    const int g2 = lane >> 2, c4 = lane & 3;

    if (!FUSED) {
        if (!producer) {
#pragma unroll
            for (int m = 0; m < 2; m++) {
#pragma unroll
                for (int nt = 0; nt < 4; nt++) {
                    int row0 = n0 + warpM * 32 + m * 16 + g2;
                    int col  = warpN * 32 + nt * 8 + c4 * 2;
                    *reinterpret_cast<float2*>(xout + (size_t)row0 * HID + col) =
                        make_float2(acc[m][nt][0], acc[m][nt][1]);
                    *reinterpret_cast<float2*>(xout + (size_t)(row0 + 8) * HID + col) =
                        make_float2(acc[m][nt][2], acc[m][nt][3]);
                }
            }
        }
    } else {
        __syncthreads();               // all mma reads of smem done
        float* hsm = reinterpret_cast<float*>(sm);          // [128][66]
        float* wsm = reinterpret_cast<float*>(sm + 33792);  // [64][40]
        for (int q = tid; q < HID * OUTF; q += 384) wsm[q] = Wout[q];
        if (!producer) {
#pragma unroll
            for (int m = 0; m < 2; m++) {
#pragma unroll
                for (int nt = 0; nt < 4; nt++) {
                    int row = warpM * 32 + m * 16 + g2;
                    int col = warpN * 32 + nt * 8 + c4 * 2;
                    *reinterpret_cast<float2*>(hsm + row * 66 + col) =
                        make_float2(acc[m][nt][0], acc[m][nt][1]);
                    *reinterpret_cast<float2*>(hsm + (row + 8) * 66 + col) =
                        make_float2(acc[m][nt][2], acc[m][nt][3]);
                }
            }
        }
        __syncthreads();

        if (tid < 256) {
            const int node = tid >> 1;
            const int half = tid & 1;
            float v[20];
#pragma unroll
            for (int q = 0; q < 20; q++) v[q] = 0.f;
#pragma unroll 8
            for (int i = 0; i < HID; i++) {
                float h = hsm[node * 66 + i];
                const float4* wr = reinterpret_cast<const float4*>(
                    wsm + i * OUTF + half * 20);
#pragma unroll
                for (int q = 0; q < 5; q++) {
                    float4 w = wr[q];
                    v[4*q+0] += h * w.x; v[4*q+1] += h * w.y;
                    v[4*q+2] += h * w.z; v[4*q+3] += h * w.w;
                }
            }
            float mx = v[0];
#pragma unroll
            for (int q = 1; q < 20; q++) mx = fmaxf(mx, v[q]);
            mx = fmaxf(mx, __shfl_xor_sync(0xFFFFFFFFu, mx, 1));
            float e = 0.f;
#pragma unroll
            for (int q = 0; q < 20; q++) e += __expf(v[q] - mx);
            e += __shfl_xor_sync(0xFFFFFFFFu, e, 1);
            float ls = mx + __logf(e);
            int gn = n0 + node;
            if (gn < NN) {
                float* dst = outp + (size_t)gn * OUTF + half * 20;
#pragma unroll
                for (int q = 0; q < 20; q++) dst[q] = v[q] - ls;
            }
        }
    }
}

// ---------------------------------------------------------------------------
extern "C" void kernel_launch(void* const* d_in, const int* in_sizes, int n_in,
                              void* d_out, int out_size)
{
    const float* x     = (const float*)d_in[0];
    const int*   erow  = (const int*)  d_in[1];
    const int*   ecol  = (const int*)  d_in[2];
    const float* ew    = (const float*)d_in[3];
    const float* W_in  = (const float*)d_in[4];
    const float* b_in  = (const float*)d_in[5];
    const float* c1    = (const float*)d_in[6];
    const float* c2    = (const float*)d_in[7];
    const float* W_out = (const float*)d_in[8];
    float* out = (float*)d_out;

    float *bufA = nullptr, *bufB = nullptr;
    unsigned short *chp = nullptr, *clp = nullptr;
    cudaGetSymbolAddress((void**)&bufA, g_bufA);
    cudaGetSymbolAddress((void**)&bufB, g_bufB);
    cudaGetSymbolAddress((void**)&chp,  g_Ch);
    cudaGetSymbolAddress((void**)&clp,  g_Cl);

    cudaFuncSetAttribute(kan_mma_kernel<false>,
                         cudaFuncAttributeMaxDynamicSharedMemorySize, KAN_SMEM);
    cudaFuncSetAttribute(kan_mma_kernel<true>,
                         cudaFuncAttributeMaxDynamicSharedMemorySize, KAN_SMEM);

    const int kanBlocks  = NNP / 128;          // 782
    const int spmmBlocks = (NN + 7) / 8;
    const size_t cl_sz   = (size_t)16 * 64 * 64;   // entries per layer

    build_csr_kernel<<<NB, 256>>>(erow, ecol, ew, c1, c2);              // 0
    lin_in_kernel<<<NN / 16, 256>>>(x, W_in, b_in);                     // 1
    spmm_csr_kernel<<<spmmBlocks, 256>>>(bufA, bufB);                   // 2
    kan_mma_kernel<false><<<kanBlocks, 384, KAN_SMEM>>>(
        bufB, chp, clp, bufA, nullptr, nullptr);                        // 3 <- profiled
    spmm_csr_kernel<<<spmmBlocks, 256>>>(bufA, bufB);                   // 4
    kan_mma_kernel<true><<<kanBlocks, 384, KAN_SMEM>>>(
        bufB, chp + cl_sz, clp + cl_sz, nullptr, W_out, out);           // 5
}